// round 9
// baseline (speedup 1.0000x reference)
#include <cuda_runtime.h>
#include <math.h>
#include <stdint.h>

#define NP   50000
#define NL   10000
#define LSEQ 8
#define DEG  40
#define DD   64
#define FULL 0xffffffffu
#define MCTA 128          // paths per CTA in mma path kernel
#define ASTR 36           // u32 row stride of split-h arrays (bank-conflict-free)

// ---- persistent scratch (device globals: allocation-free) ----
__device__ float g_path_state[NP * DD];
__device__ float g_link_state[NL * DD];
__device__ float g_link_proj[NL * 192];              // x-proj with z/r biases folded in
__device__ float g_path_sum[NL * DD];
__device__ float g_psseq[(size_t)NP * 8 * DD];       // slots = steps 1..8
__device__ uint2 g_BpackH[4 * 24 * 32];              // Wh hi bf16x2 fragment pack (24KB)
__device__ uint2 g_BpackL[4 * 24 * 32];              // Wh lo residual pack (24KB)

__device__ __forceinline__ float sigmoidf_(float x) { return 1.0f / (1.0f + expf(-x)); }

__device__ __forceinline__ float fast_ex2(float x) {
    float r; asm("ex2.approx.f32 %0, %1;" : "=f"(r) : "f"(x)); return r;
}
__device__ __forceinline__ float fast_rcp(float x) {
    float r; asm("rcp.approx.f32 %0, %1;" : "=f"(r) : "f"(x)); return r;
}
__device__ __forceinline__ float fsig(float x) {
    return fast_rcp(1.f + fast_ex2(-1.4426950408889634f * x));
}
__device__ __forceinline__ float ftanh(float x) {
    return 1.f - 2.f * fast_rcp(1.f + fast_ex2(2.8853900817779268f * x));
}
__device__ __forceinline__ float gru_one(float zp, float rp, float hp, float xh, float ho) {
    float z = fsig(zp), r = fsig(rp);
    float gg = ftanh(xh + r * hp);
    return z * ho + (1.f - z) * gg;
}

// pack lo->lower16, hi->upper16 bf16x2
__device__ __forceinline__ uint32_t pack_bf16x2(float lo, float hi) {
    uint32_t r; asm("cvt.rn.bf16x2.f32 %0, %1, %2;" : "=r"(r) : "f"(hi), "f"(lo)); return r;
}
__device__ __forceinline__ void split2(float a, float b, uint32_t& hi, uint32_t& lo) {
    hi = pack_bf16x2(a, b);
    float ra = a - __uint_as_float(hi << 16);
    float rb = b - __uint_as_float(hi & 0xffff0000u);
    lo = pack_bf16x2(ra, rb);
}

// NOTE: intentionally NOT volatile — pure register computation, lets ptxas schedule.
#define MMA_BF16(c, a0, a1, a2, a3, b0, b1)                                   \
    asm("mma.sync.aligned.m16n8k16.row.col.f32.bf16.bf16.f32 "                \
        "{%0,%1,%2,%3}, {%4,%5,%6,%7}, {%8,%9}, {%0,%1,%2,%3};"               \
        : "+f"((c)[0]), "+f"((c)[1]), "+f"((c)[2]), "+f"((c)[3])              \
        : "r"(a0), "r"(a1), "r"(a2), "r"(a3), "r"(b0), "r"(b1))

// ============================================================
// Path embedding: 3 -> 64 -> 64 MLP (relu), warp per path
// ============================================================
__global__ void path_embed_kernel(const float* __restrict__ ft, const float* __restrict__ fp,
                                  const float* __restrict__ fps,
                                  const float* __restrict__ w1, const float* __restrict__ b1,
                                  const float* __restrict__ w2, const float* __restrict__ b2)
{
    __shared__ float s_w2[DD * DD];
    __shared__ float s_w1[3 * DD];
    __shared__ float s_b1[DD];
    __shared__ float s_b2[DD];
    for (int i = threadIdx.x; i < DD * DD; i += blockDim.x) s_w2[i] = w2[i];
    for (int i = threadIdx.x; i < 3 * DD; i += blockDim.x) s_w1[i] = w1[i];
    for (int i = threadIdx.x; i < DD; i += blockDim.x) { s_b1[i] = b1[i]; s_b2[i] = b2[i]; }
    __syncthreads();

    int warp = threadIdx.x >> 5, lane = threadIdx.x & 31;
    int p = blockIdx.x * 8 + warp;
    if (p >= NP) return;
    int d0 = 2 * lane, d1 = d0 + 1;

    float in0 = ft[p] * 1e-4f;
    float in1 = fp[p] * 1e-3f;
    float in2 = fps[p] * 1e-3f;

    float ha = fmaxf(0.f, s_b1[d0] + in0 * s_w1[d0] + in1 * s_w1[DD + d0] + in2 * s_w1[2 * DD + d0]);
    float hb = fmaxf(0.f, s_b1[d1] + in0 * s_w1[d1] + in1 * s_w1[DD + d1] + in2 * s_w1[2 * DD + d1]);

    float oa = s_b2[d0], ob = s_b2[d1];
    #pragma unroll 8
    for (int kk = 0; kk < 32; kk++) {
        float ka = __shfl_sync(FULL, ha, kk);
        float kb = __shfl_sync(FULL, hb, kk);
        float2 wA = *(const float2*)&s_w2[(2 * kk) * DD + d0];
        float2 wB = *(const float2*)&s_w2[(2 * kk + 1) * DD + d0];
        oa += ka * wA.x + kb * wB.x;
        ob += ka * wA.y + kb * wB.y;
    }
    g_path_state[p * DD + d0] = fmaxf(0.f, oa);
    g_path_state[p * DD + d1] = fmaxf(0.f, ob);
}

// ============================================================
// Link embedding
// ============================================================
__global__ void link_embed_kernel(const float* __restrict__ ftraf, const float* __restrict__ cap,
                                  const int* __restrict__ p2l,
                                  const float* __restrict__ w1, const float* __restrict__ b1,
                                  const float* __restrict__ w2, const float* __restrict__ b2)
{
    __shared__ float s_w2[DD * DD];
    __shared__ float s_w1[2 * DD];
    __shared__ float s_b1[DD];
    __shared__ float s_b2[DD];
    for (int i = threadIdx.x; i < DD * DD; i += blockDim.x) s_w2[i] = w2[i];
    for (int i = threadIdx.x; i < 2 * DD; i += blockDim.x) s_w1[i] = w1[i];
    for (int i = threadIdx.x; i < DD; i += blockDim.x) { s_b1[i] = b1[i]; s_b2[i] = b2[i]; }
    __syncthreads();

    int warp = threadIdx.x >> 5, lane = threadIdx.x & 31;
    int l = blockIdx.x * 8 + warp;
    if (l >= NL) return;
    int d0 = 2 * lane, d1 = d0 + 1;

    float s = ftraf[p2l[(l * DEG + lane) * 2]];
    if (lane < DEG - 32) s += ftraf[p2l[(l * DEG + 32 + lane) * 2]];
    #pragma unroll
    for (int off = 16; off; off >>= 1) s += __shfl_xor_sync(FULL, s, off);

    float c = cap[l];
    float in0 = c * 1e-5f;
    float in1 = s / (c * 1e9f);

    float ha = fmaxf(0.f, s_b1[d0] + in0 * s_w1[d0] + in1 * s_w1[DD + d0]);
    float hb = fmaxf(0.f, s_b1[d1] + in0 * s_w1[d1] + in1 * s_w1[DD + d1]);

    float oa = s_b2[d0], ob = s_b2[d1];
    #pragma unroll 8
    for (int kk = 0; kk < 32; kk++) {
        float ka = __shfl_sync(FULL, ha, kk);
        float kb = __shfl_sync(FULL, hb, kk);
        float2 wA = *(const float2*)&s_w2[(2 * kk) * DD + d0];
        float2 wB = *(const float2*)&s_w2[(2 * kk + 1) * DD + d0];
        oa += ka * wA.x + kb * wB.x;
        ob += ka * wA.y + kb * wB.y;
    }
    g_link_state[l * DD + d0] = fmaxf(0.f, oa);
    g_link_state[l * DD + d1] = fmaxf(0.f, ob);
}

// ============================================================
// Prepack pg_wh into split-bf16 m16n8k16 B-fragment order,
// hi and lo in SEPARATE arrays (uint2 per (kt,nt,lane)).
// ============================================================
__global__ void prepack_wh_kernel(const float* __restrict__ wh)
{
    int i = blockIdx.x * 256 + threadIdx.x;
    if (i >= 4 * 24 * 32) return;
    int lane = i & 31;
    int nt = (i >> 5) % 24;
    int kt = i / (32 * 24);
    int q = lane & 3, g = lane >> 2;
    int n = nt * 8 + g;
    int k0 = kt * 16 + 2 * q;

    float2 f0 = make_float2(wh[k0 * 192 + n],       wh[(k0 + 1) * 192 + n]);
    float2 f1 = make_float2(wh[(k0 + 8) * 192 + n], wh[(k0 + 9) * 192 + n]);
    uint32_t b0h, b0l, b1h, b1l;
    split2(f0.x, f0.y, b0h, b0l);
    split2(f1.x, f1.y, b1h, b1l);
    g_BpackH[i] = make_uint2(b0h, b1h);
    g_BpackL[i] = make_uint2(b0l, b1l);
}

// ============================================================
// link_proj = link_state @ pg_wx + pg_bx (+ pg_bh folded for z/r)
// warp = 5 links -> 250 CTAs (single wave at 2 CTAs/SM)
// ============================================================
#define HALF_SMEM_BYTES ((DD * 192 + 192) * 4)

__global__ void __launch_bounds__(256, 2)
link_proj_kernel(const float* __restrict__ wx_g, const float* __restrict__ bx_g,
                 const float* __restrict__ bh_g)
{
    extern __shared__ float sm[];
    float* s_wx = sm;
    float* s_bx = sm + DD * 192;
    for (int i = threadIdx.x; i < DD * 192; i += 256) s_wx[i] = wx_g[i];
    if (threadIdx.x < 192)
        s_bx[threadIdx.x] = bx_g[threadIdx.x] +
                            (threadIdx.x < 128 ? bh_g[threadIdx.x] : 0.f);
    __syncthreads();

    int warp = threadIdx.x >> 5, lane = threadIdx.x & 31;
    int d0 = 2 * lane;
    int l0 = blockIdx.x * 40 + warp * 5;

    float h0[5], h1[5];
    #pragma unroll
    for (int b = 0; b < 5; b++) {
        int l = l0 + b;
        h0[b] = h1[b] = 0.f;
        if (l < NL) {
            float2 h = *(const float2*)&g_link_state[l * DD + d0];
            h0[b] = h.x; h1[b] = h.y;
        }
    }

    float pz0[5], pz1[5], pr0[5], pr1[5], ph0[5], ph1[5];
    #pragma unroll
    for (int b = 0; b < 5; b++) {
        pz0[b] = s_bx[d0];        pz1[b] = s_bx[d0 + 1];
        pr0[b] = s_bx[64 + d0];   pr1[b] = s_bx[64 + d0 + 1];
        ph0[b] = s_bx[128 + d0];  ph1[b] = s_bx[128 + d0 + 1];
    }
    #pragma unroll 4
    for (int kk = 0; kk < 32; kk++) {
        const float* wa = s_wx + (2 * kk) * 192;
        float2 za = *(const float2*)(wa + d0);
        float2 ra = *(const float2*)(wa + 64 + d0);
        float2 ha = *(const float2*)(wa + 128 + d0);
        float2 zb = *(const float2*)(wa + 192 + d0);
        float2 rb = *(const float2*)(wa + 192 + 64 + d0);
        float2 hb = *(const float2*)(wa + 192 + 128 + d0);
        #pragma unroll
        for (int b = 0; b < 5; b++) {
            float ka = __shfl_sync(FULL, h0[b], kk);
            float kb = __shfl_sync(FULL, h1[b], kk);
            pz0[b] += ka * za.x + kb * zb.x;  pz1[b] += ka * za.y + kb * zb.y;
            pr0[b] += ka * ra.x + kb * rb.x;  pr1[b] += ka * ra.y + kb * rb.y;
            ph0[b] += ka * ha.x + kb * hb.x;  ph1[b] += ka * ha.y + kb * hb.y;
        }
    }
    #pragma unroll
    for (int b = 0; b < 5; b++) {
        int l = l0 + b;
        if (l < NL) {
            *(float2*)&g_link_proj[l * 192 + d0]       = make_float2(pz0[b], pz1[b]);
            *(float2*)&g_link_proj[l * 192 + 64 + d0]  = make_float2(pr0[b], pr1[b]);
            *(float2*)&g_link_proj[l * 192 + 128 + d0] = make_float2(ph0[b], ph1[b]);
        }
    }
}

// ============================================================
// Path GRU via split-bf16 m16n8k16 mma. CTA = 128 paths, 8 warps.
// Per kt: THREE PASSES over all 24 nt (hi*hi, hi*lo, lo*hi) so
// consecutive MMAs never share a C tile (RAW distance ~24).
// ============================================================
#define PSM_A_HI  49152
#define PSM_A_LO  (PSM_A_HI + MCTA * ASTR * 4)
#define PSM_BHH   (PSM_A_LO + MCTA * ASTR * 4)
#define MMA_SMEM_BYTES (PSM_BHH + 64 * 4)

__global__ void __launch_bounds__(256, 2)
path_update_mma_kernel(const int* __restrict__ l2p, const float* __restrict__ bh_g, int first)
{
    extern __shared__ unsigned char smraw[];
    uint2*    s_Bh  = (uint2*)smraw;                      // 3072 uint2 = 24 KB
    uint2*    s_Bl  = (uint2*)(smraw + 24576);            // 24 KB
    uint32_t* s_Ahi = (uint32_t*)(smraw + PSM_A_HI);      // 128 x ASTR
    uint32_t* s_Alo = (uint32_t*)(smraw + PSM_A_LO);
    float*    s_bhh = (float*)(smraw + PSM_BHH);          // 64

    int tid = threadIdx.x;
    #pragma unroll
    for (int i = 0; i < 12; i++) {
        s_Bh[tid + i * 256] = g_BpackH[tid + i * 256];
        s_Bl[tid + i * 256] = g_BpackL[tid + i * 256];
    }
    if (tid < 64) s_bhh[tid] = bh_g[128 + tid];

    // prologue: load h rows (fp32), split to bf16x2 hi/lo arrays.
    int pbase = blockIdx.x * MCTA;
    {
        int r = tid >> 1, hf = tid & 1;
        int p = pbase + r;
        int pc = p < NP ? p : NP - 1;
        const float* hsrc = (first ? &g_path_state[(size_t)pc * 64]
                                   : &g_psseq[((size_t)pc * 8 + 7) * 64]) + hf * 32;
        uint32_t* ah = &s_Ahi[r * ASTR + hf * 16];
        uint32_t* al = &s_Alo[r * ASTR + hf * 16];
        #pragma unroll
        for (int j = 0; j < 8; j++) {
            float4 v = *(const float4*)&hsrc[4 * j];
            uint32_t h0, l0, h1, l1;
            split2(v.x, v.y, h0, l0);
            split2(v.z, v.w, h1, l1);
            ah[2 * j] = h0; ah[2 * j + 1] = h1;
            al[2 * j] = l0; al[2 * j + 1] = l1;
        }
    }
    __syncthreads();

    int lane = tid & 31, warp = tid >> 5;
    int q = lane & 3, g = lane >> 2;
    int r0 = warp * 16 + g;                 // local rows r0, r0+8
    int p0 = pbase + r0, p1 = p0 + 8;
    int p0c = (p0 < NP) ? p0 : 0;
    int p1c = (p1 < NP) ? p1 : 0;

    const uint32_t* A0hi = &s_Ahi[r0 * ASTR];
    const uint32_t* A1hi = &s_Ahi[(r0 + 8) * ASTR];
    const uint32_t* A0lo = &s_Alo[r0 * ASTR];
    const uint32_t* A1lo = &s_Alo[(r0 + 8) * ASTR];

    float C[24][4];

    for (int t = 0; t < LSEQ; t++) {
        int li0 = l2p[p0c * LSEQ + t];
        int li1 = l2p[p1c * LSEQ + t];
        const float* pr0 = &g_link_proj[li0 * 192];
        const float* pr1 = &g_link_proj[li1 * 192];

        // C init: z,r tiles <- gathered x-projection (biases pre-folded);
        // hh tiles <- 0 (bhh added in epilogue).
        #pragma unroll
        for (int nt = 0; nt < 16; nt++) {
            int col = nt * 8 + 2 * q;
            float2 x0 = *(const float2*)&pr0[col];
            float2 x1 = *(const float2*)&pr1[col];
            C[nt][0] = x0.x; C[nt][1] = x0.y;
            C[nt][2] = x1.x; C[nt][3] = x1.y;
        }
        #pragma unroll
        for (int nt = 16; nt < 24; nt++) {
            C[nt][0] = 0.f; C[nt][1] = 0.f; C[nt][2] = 0.f; C[nt][3] = 0.f;
        }

        // h @ Wh via split-bf16, RAW-chain-free ordering
        #pragma unroll
        for (int kt = 0; kt < 4; kt++) {
            int kp = kt * 8 + q;
            uint32_t a0h = A0hi[kp],     a1h = A1hi[kp];
            uint32_t a2h = A0hi[kp + 4], a3h = A1hi[kp + 4];
            uint32_t a0l = A0lo[kp],     a1l = A1lo[kp];
            uint32_t a2l = A0lo[kp + 4], a3l = A1lo[kp + 4];
            const uint2* Bh = s_Bh + kt * 24 * 32 + lane;
            const uint2* Bl = s_Bl + kt * 24 * 32 + lane;
            #pragma unroll
            for (int nt = 0; nt < 24; nt++) {
                uint2 B = Bh[nt * 32];
                MMA_BF16(C[nt], a0h, a1h, a2h, a3h, B.x, B.y);
            }
            #pragma unroll
            for (int nt = 0; nt < 24; nt++) {
                uint2 B = Bl[nt * 32];
                MMA_BF16(C[nt], a0h, a1h, a2h, a3h, B.x, B.y);
            }
            #pragma unroll
            for (int nt = 0; nt < 24; nt++) {
                uint2 B = Bh[nt * 32];
                MMA_BF16(C[nt], a0l, a1l, a2l, a3l, B.x, B.y);
            }
        }

        // elementwise GRU update + writeback
        #pragma unroll
        for (int j = 0; j < 8; j++) {
            int col = j * 8 + 2 * q;
            int kp = j * 4 + q;
            float2 xh0 = *(const float2*)&pr0[128 + col];
            float2 xh1 = *(const float2*)&pr1[128 + col];
            float2 bhh = *(const float2*)&s_bhh[col];
            uint32_t ohi0 = A0hi[kp], ohi1 = A1hi[kp];
            uint32_t olo0 = A0lo[kp], olo1 = A1lo[kp];
            float ho00 = __uint_as_float(ohi0 << 16)         + __uint_as_float(olo0 << 16);
            float ho01 = __uint_as_float(ohi0 & 0xffff0000u) + __uint_as_float(olo0 & 0xffff0000u);
            float ho10 = __uint_as_float(ohi1 << 16)         + __uint_as_float(olo1 << 16);
            float ho11 = __uint_as_float(ohi1 & 0xffff0000u) + __uint_as_float(olo1 & 0xffff0000u);

            float n00 = gru_one(C[j][0], C[j + 8][0], C[j + 16][0] + bhh.x, xh0.x, ho00);
            float n01 = gru_one(C[j][1], C[j + 8][1], C[j + 16][1] + bhh.y, xh0.y, ho01);
            float n10 = gru_one(C[j][2], C[j + 8][2], C[j + 16][2] + bhh.x, xh1.x, ho10);
            float n11 = gru_one(C[j][3], C[j + 8][3], C[j + 16][3] + bhh.y, xh1.y, ho11);

            if (p0 < NP) *(float2*)&g_psseq[((size_t)p0 * 8 + t) * 64 + col] = make_float2(n00, n01);
            if (p1 < NP) *(float2*)&g_psseq[((size_t)p1 * 8 + t) * 64 + col] = make_float2(n10, n11);

            uint32_t nh0, nl0, nh1, nl1;
            split2(n00, n01, nh0, nl0);
            split2(n10, n11, nh1, nl1);
            ((uint32_t*)A0hi)[kp] = nh0; ((uint32_t*)A1hi)[kp] = nh1;
            ((uint32_t*)A0lo)[kp] = nl0; ((uint32_t*)A1lo)[kp] = nl1;
        }
        __syncwarp();   // warp-private rows: order smem h writes before next step's reads
    }
}

// ============================================================
// Gather-sum: path_sum[l] = sum over DEG entries of psseq rows.
// ============================================================
__global__ void __launch_bounds__(256)
gather_sum_kernel(const int* __restrict__ p2l)
{
    __shared__ int2 s_idx[4 * DEG];
    int lbase = blockIdx.x * 4;
    for (int i = threadIdx.x; i < 4 * DEG; i += 256) {
        int ll = lbase + i / DEG;
        if (ll < NL) s_idx[i] = ((const int2*)p2l)[ll * DEG + (i % DEG)];
    }
    __syncthreads();

    int sub = threadIdx.x >> 6;
    int d   = threadIdx.x & 63;
    int l = lbase + sub;
    if (l >= NL) return;

    float s = 0.f;
    #pragma unroll 8
    for (int e = 0; e < DEG; e++) {
        int2 pe = s_idx[sub * DEG + e];
        s += g_psseq[((size_t)pe.x * 8 + (pe.y - 1)) * DD + d];
    }
    g_path_sum[l * DD + d] = s;
}

// ============================================================
// Link GRU on precomputed path_sum. warp = 5 links -> 250 CTAs.
// ============================================================
#define GRU_SMEM_BYTES ((2 * DD * 192 + 2 * 192) * 4)

__global__ void __launch_bounds__(256, 2)
link_gru_kernel(const float* __restrict__ wx_g, const float* __restrict__ wh_g,
                const float* __restrict__ bx_g, const float* __restrict__ bh_g)
{
    extern __shared__ float sm[];
    float* s_wx = sm;
    float* s_wh = sm + DD * 192;
    float* s_bx = s_wh + DD * 192;
    float* s_bh = s_bx + 192;
    for (int i = threadIdx.x; i < DD * 192; i += 256) { s_wx[i] = wx_g[i]; s_wh[i] = wh_g[i]; }
    if (threadIdx.x < 192) { s_bx[threadIdx.x] = bx_g[threadIdx.x]; s_bh[threadIdx.x] = bh_g[threadIdx.x]; }
    __syncthreads();

    int warp = threadIdx.x >> 5, lane = threadIdx.x & 31;
    int d0 = 2 * lane;
    int l0 = blockIdx.x * 40 + warp * 5;

    float h0[5], h1[5], x0[5], x1[5];
    #pragma unroll
    for (int b = 0; b < 5; b++) {
        int l = l0 + b;
        h0[b] = h1[b] = x0[b] = x1[b] = 0.f;
        if (l < NL) {
            float2 h = *(const float2*)&g_link_state[l * DD + d0];
            float2 x = *(const float2*)&g_path_sum[l * DD + d0];
            h0[b] = h.x; h1[b] = h.y; x0[b] = x.x; x1[b] = x.y;
        }
    }

    float bz0 = s_bx[d0] + s_bh[d0],               bz1 = s_bx[d0 + 1] + s_bh[d0 + 1];
    float br0 = s_bx[64 + d0] + s_bh[64 + d0],     br1 = s_bx[64 + d0 + 1] + s_bh[64 + d0 + 1];
    float bxh0 = s_bx[128 + d0],  bxh1 = s_bx[128 + d0 + 1];
    float bhh0 = s_bh[128 + d0],  bhh1 = s_bh[128 + d0 + 1];

    float az0[5], az1[5], ar0[5], ar1[5], ax0[5], ax1[5], ah0[5], ah1[5];
    #pragma unroll
    for (int b = 0; b < 5; b++) {
        az0[b] = bz0;  az1[b] = bz1;  ar0[b] = br0;  ar1[b] = br1;
        ax0[b] = bxh0; ax1[b] = bxh1; ah0[b] = bhh0; ah1[b] = bhh1;
    }
    #pragma unroll 2
    for (int kk = 0; kk < 32; kk++) {
        const float* wxa = s_wx + (2 * kk) * 192;
        const float* wha = s_wh + (2 * kk) * 192;
        float2 xza = *(const float2*)(wxa + d0);
        float2 xra = *(const float2*)(wxa + 64 + d0);
        float2 xha = *(const float2*)(wxa + 128 + d0);
        float2 xzb = *(const float2*)(wxa + 192 + d0);
        float2 xrb = *(const float2*)(wxa + 192 + 64 + d0);
        float2 xhb = *(const float2*)(wxa + 192 + 128 + d0);
        float2 hza = *(const float2*)(wha + d0);
        float2 hra = *(const float2*)(wha + 64 + d0);
        float2 hha = *(const float2*)(wha + 128 + d0);
        float2 hzb = *(const float2*)(wha + 192 + d0);
        float2 hrb = *(const float2*)(wha + 192 + 64 + d0);
        float2 hhb = *(const float2*)(wha + 192 + 128 + d0);
        #pragma unroll
        for (int b = 0; b < 5; b++) {
            float xka = __shfl_sync(FULL, x0[b], kk);
            float xkb = __shfl_sync(FULL, x1[b], kk);
            float hka = __shfl_sync(FULL, h0[b], kk);
            float hkb = __shfl_sync(FULL, h1[b], kk);
            az0[b] += xka * xza.x + xkb * xzb.x + hka * hza.x + hkb * hzb.x;
            az1[b] += xka * xza.y + xkb * xzb.y + hka * hza.y + hkb * hzb.y;
            ar0[b] += xka * xra.x + xkb * xrb.x + hka * hra.x + hkb * hrb.x;
            ar1[b] += xka * xra.y + xkb * xrb.y + hka * hra.y + hkb * hrb.y;
            ax0[b] += xka * xha.x + xkb * xhb.x;
            ax1[b] += xka * xha.y + xkb * xhb.y;
            ah0[b] += hka * hha.x + hkb * hhb.x;
            ah1[b] += hka * hha.y + hkb * hhb.y;
        }
    }
    #pragma unroll
    for (int b = 0; b < 5; b++) {
        int l = l0 + b;
        if (l < NL) {
            float z0 = sigmoidf_(az0[b]), z1 = sigmoidf_(az1[b]);
            float r0 = sigmoidf_(ar0[b]), r1 = sigmoidf_(ar1[b]);
            float g0 = tanhf(ax0[b] + r0 * ah0[b]);
            float g1 = tanhf(ax1[b] + r1 * ah1[b]);
            float n0 = z0 * h0[b] + (1.f - z0) * g0;
            float n1 = z1 * h1[b] + (1.f - z1) * g1;
            *(float2*)&g_link_state[l * DD + d0] = make_float2(n0, n1);
        }
    }
}

// ============================================================
// Readout
// ============================================================
__global__ void readout_kernel(const int* __restrict__ l2p, const float* __restrict__ cap,
                               const float* __restrict__ w1, const float* __restrict__ b1,
                               const float* __restrict__ w2, const float* __restrict__ b2,
                               const float* __restrict__ w3, const float* __restrict__ b3,
                               float* __restrict__ out)
{
    __shared__ float s_w1[DD * 32];
    __shared__ float s_w2[32 * 16];
    __shared__ float s_w3[16];
    __shared__ float s_b1[32];
    __shared__ float s_b2[16];
    __shared__ float s_b3;
    for (int i = threadIdx.x; i < DD * 32; i += blockDim.x) s_w1[i] = w1[i];
    for (int i = threadIdx.x; i < 32 * 16; i += blockDim.x) s_w2[i] = w2[i];
    if (threadIdx.x < 16) { s_w3[threadIdx.x] = w3[threadIdx.x]; s_b2[threadIdx.x] = b2[threadIdx.x]; }
    if (threadIdx.x < 32) s_b1[threadIdx.x] = b1[threadIdx.x];
    if (threadIdx.x == 0) s_b3 = b3[0];
    __syncthreads();

    int warp = threadIdx.x >> 5, lane = threadIdx.x & 31;
    int p = blockIdx.x * 8 + warp;
    if (p >= NP) return;
    int d0 = 2 * lane;

    float delay = 0.f;
    for (int t = 0; t < LSEQ; t++) {
        float2 in = *(const float2*)&g_psseq[((size_t)p * 8 + t) * DD + d0];
        float a = s_b1[lane];
        #pragma unroll 8
        for (int kk = 0; kk < 32; kk++) {
            float ka = __shfl_sync(FULL, in.x, kk);
            float kb = __shfl_sync(FULL, in.y, kk);
            a += ka * s_w1[(2 * kk) * 32 + lane] + kb * s_w1[(2 * kk + 1) * 32 + lane];
        }
        a = fmaxf(a, 0.f);
        float c = s_b2[lane & 15];
        #pragma unroll 8
        for (int k = 0; k < 32; k++) {
            float hk = __shfl_sync(FULL, a, k);
            c += hk * s_w2[k * 16 + (lane & 15)];
        }
        c = fmaxf(c, 0.f);
        float term = (lane < 16) ? c * s_w3[lane] : 0.f;
        #pragma unroll
        for (int off = 16; off; off >>= 1) term += __shfl_xor_sync(FULL, term, off);
        float xo = term + s_b3;
        float occ = fmaxf(xo, 0.f) + log1pf(expf(-fabsf(xo)));
        int li = l2p[p * LSEQ + t];
        delay += occ / cap[li];
    }
    if (lane == 0) out[p] = delay;
}

// ============================================================
// Launch
// ============================================================
extern "C" void kernel_launch(void* const* d_in, const int* in_sizes, int n_in,
                              void* d_out, int out_size)
{
    const float* ft    = (const float*)d_in[0];
    const float* fpk   = (const float*)d_in[1];
    const float* fps   = (const float*)d_in[2];
    const float* cap   = (const float*)d_in[3];
    const int*   l2p   = (const int*)d_in[4];
    const int*   p2l   = (const int*)d_in[5];
    const float* pe_w1 = (const float*)d_in[6],  *pe_b1 = (const float*)d_in[7];
    const float* pe_w2 = (const float*)d_in[8],  *pe_b2 = (const float*)d_in[9];
    const float* le_w1 = (const float*)d_in[10], *le_b1 = (const float*)d_in[11];
    const float* le_w2 = (const float*)d_in[12], *le_b2 = (const float*)d_in[13];
    const float* pg_wx = (const float*)d_in[14], *pg_wh = (const float*)d_in[15];
    const float* pg_bx = (const float*)d_in[16], *pg_bh = (const float*)d_in[17];
    const float* lg_wx = (const float*)d_in[18], *lg_wh = (const float*)d_in[19];
    const float* lg_bx = (const float*)d_in[20], *lg_bh = (const float*)d_in[21];
    const float* ro_w1 = (const float*)d_in[22], *ro_b1 = (const float*)d_in[23];
    const float* ro_w2 = (const float*)d_in[24], *ro_b2 = (const float*)d_in[25];
    const float* ro_w3 = (const float*)d_in[26], *ro_b3 = (const float*)d_in[27];

    cudaFuncSetAttribute(link_proj_kernel,       cudaFuncAttributeMaxDynamicSharedMemorySize, HALF_SMEM_BYTES);
    cudaFuncSetAttribute(path_update_mma_kernel, cudaFuncAttributeMaxDynamicSharedMemorySize, MMA_SMEM_BYTES);
    cudaFuncSetAttribute(link_gru_kernel,        cudaFuncAttributeMaxDynamicSharedMemorySize, GRU_SMEM_BYTES);

    path_embed_kernel<<<(NP + 7) / 8, 256>>>(ft, fpk, fps, pe_w1, pe_b1, pe_w2, pe_b2);
    link_embed_kernel<<<(NL + 7) / 8, 256>>>(ft, cap, p2l, le_w1, le_b1, le_w2, le_b2);
    prepack_wh_kernel<<<(4 * 24 * 32 + 255) / 256, 256>>>(pg_wh);

    for (int it = 0; it < 8; it++) {
        link_proj_kernel<<<(NL + 39) / 40, 256, HALF_SMEM_BYTES>>>(pg_wx, pg_bx, pg_bh);
        path_update_mma_kernel<<<(NP + MCTA - 1) / MCTA, 256, MMA_SMEM_BYTES>>>(
            l2p, pg_bh, it == 0 ? 1 : 0);
        gather_sum_kernel<<<(NL + 3) / 4, 256>>>(p2l);
        link_gru_kernel<<<(NL + 39) / 40, 256, GRU_SMEM_BYTES>>>(
            lg_wx, lg_wh, lg_bx, lg_bh);
    }

    readout_kernel<<<(NP + 7) / 8, 256>>>(l2p, cap, ro_w1, ro_b1, ro_w2, ro_b2, ro_w3, ro_b3,
                                          (float*)d_out);
}

// round 10
// speedup vs baseline: 1.1232x; 1.1232x over previous
#include <cuda_runtime.h>
#include <math.h>
#include <stdint.h>

#define NP   50000
#define NL   10000
#define LSEQ 8
#define DEG  40
#define DD   64
#define FULL 0xffffffffu
#define MCTA 128          // paths per CTA in mma path kernel
#define ASTR 36           // u32 row stride of split-h arrays (bank-conflict-free)

// ---- persistent scratch (device globals: allocation-free) ----
__device__ float g_path_state[NP * DD];
__device__ float g_link_state[NL * DD];
__device__ float g_link_proj[NL * 192];              // x-proj with z/r biases folded in
__device__ float g_path_sum[NL * DD];
__device__ float g_psseq[(size_t)NP * 8 * DD];       // slots = steps 1..8
__device__ uint4 g_Bpack[4 * 24 * 32];               // Wh split-bf16 fragment pack (48KB)

__device__ __forceinline__ float sigmoidf_(float x) { return 1.0f / (1.0f + expf(-x)); }

__device__ __forceinline__ float fast_ex2(float x) {
    float r; asm("ex2.approx.f32 %0, %1;" : "=f"(r) : "f"(x)); return r;
}
__device__ __forceinline__ float fast_rcp(float x) {
    float r; asm("rcp.approx.f32 %0, %1;" : "=f"(r) : "f"(x)); return r;
}
__device__ __forceinline__ float fsig(float x) {
    return fast_rcp(1.f + fast_ex2(-1.4426950408889634f * x));
}
__device__ __forceinline__ float ftanh(float x) {
    return 1.f - 2.f * fast_rcp(1.f + fast_ex2(2.8853900817779268f * x));
}
__device__ __forceinline__ float gru_one(float zp, float rp, float hp, float xh, float ho) {
    float z = fsig(zp), r = fsig(rp);
    float gg = ftanh(xh + r * hp);
    return z * ho + (1.f - z) * gg;
}

// pack lo->lower16, hi->upper16 bf16x2
__device__ __forceinline__ uint32_t pack_bf16x2(float lo, float hi) {
    uint32_t r; asm("cvt.rn.bf16x2.f32 %0, %1, %2;" : "=r"(r) : "f"(hi), "f"(lo)); return r;
}
__device__ __forceinline__ void split2(float a, float b, uint32_t& hi, uint32_t& lo) {
    hi = pack_bf16x2(a, b);
    float ra = a - __uint_as_float(hi << 16);
    float rb = b - __uint_as_float(hi & 0xffff0000u);
    lo = pack_bf16x2(ra, rb);
}

#define MMA_BF16(c, a0, a1, a2, a3, b0, b1)                                   \
    asm("mma.sync.aligned.m16n8k16.row.col.f32.bf16.bf16.f32 "                \
        "{%0,%1,%2,%3}, {%4,%5,%6,%7}, {%8,%9}, {%0,%1,%2,%3};"               \
        : "+f"((c)[0]), "+f"((c)[1]), "+f"((c)[2]), "+f"((c)[3])              \
        : "r"(a0), "r"(a1), "r"(a2), "r"(a3), "r"(b0), "r"(b1))

// ============================================================
// Path embedding: 3 -> 64 -> 64 MLP (relu), warp per path
// ============================================================
__global__ void path_embed_kernel(const float* __restrict__ ft, const float* __restrict__ fp,
                                  const float* __restrict__ fps,
                                  const float* __restrict__ w1, const float* __restrict__ b1,
                                  const float* __restrict__ w2, const float* __restrict__ b2)
{
    __shared__ float s_w2[DD * DD];
    __shared__ float s_w1[3 * DD];
    __shared__ float s_b1[DD];
    __shared__ float s_b2[DD];
    for (int i = threadIdx.x; i < DD * DD; i += blockDim.x) s_w2[i] = w2[i];
    for (int i = threadIdx.x; i < 3 * DD; i += blockDim.x) s_w1[i] = w1[i];
    for (int i = threadIdx.x; i < DD; i += blockDim.x) { s_b1[i] = b1[i]; s_b2[i] = b2[i]; }
    __syncthreads();

    int warp = threadIdx.x >> 5, lane = threadIdx.x & 31;
    int p = blockIdx.x * 8 + warp;
    if (p >= NP) return;
    int d0 = 2 * lane, d1 = d0 + 1;

    float in0 = ft[p] * 1e-4f;
    float in1 = fp[p] * 1e-3f;
    float in2 = fps[p] * 1e-3f;

    float ha = fmaxf(0.f, s_b1[d0] + in0 * s_w1[d0] + in1 * s_w1[DD + d0] + in2 * s_w1[2 * DD + d0]);
    float hb = fmaxf(0.f, s_b1[d1] + in0 * s_w1[d1] + in1 * s_w1[DD + d1] + in2 * s_w1[2 * DD + d1]);

    float oa = s_b2[d0], ob = s_b2[d1];
    #pragma unroll 8
    for (int kk = 0; kk < 32; kk++) {
        float ka = __shfl_sync(FULL, ha, kk);
        float kb = __shfl_sync(FULL, hb, kk);
        float2 wA = *(const float2*)&s_w2[(2 * kk) * DD + d0];
        float2 wB = *(const float2*)&s_w2[(2 * kk + 1) * DD + d0];
        oa += ka * wA.x + kb * wB.x;
        ob += ka * wA.y + kb * wB.y;
    }
    g_path_state[p * DD + d0] = fmaxf(0.f, oa);
    g_path_state[p * DD + d1] = fmaxf(0.f, ob);
}

// ============================================================
// Link embedding
// ============================================================
__global__ void link_embed_kernel(const float* __restrict__ ftraf, const float* __restrict__ cap,
                                  const int* __restrict__ p2l,
                                  const float* __restrict__ w1, const float* __restrict__ b1,
                                  const float* __restrict__ w2, const float* __restrict__ b2)
{
    __shared__ float s_w2[DD * DD];
    __shared__ float s_w1[2 * DD];
    __shared__ float s_b1[DD];
    __shared__ float s_b2[DD];
    for (int i = threadIdx.x; i < DD * DD; i += blockDim.x) s_w2[i] = w2[i];
    for (int i = threadIdx.x; i < 2 * DD; i += blockDim.x) s_w1[i] = w1[i];
    for (int i = threadIdx.x; i < DD; i += blockDim.x) { s_b1[i] = b1[i]; s_b2[i] = b2[i]; }
    __syncthreads();

    int warp = threadIdx.x >> 5, lane = threadIdx.x & 31;
    int l = blockIdx.x * 8 + warp;
    if (l >= NL) return;
    int d0 = 2 * lane, d1 = d0 + 1;

    float s = ftraf[p2l[(l * DEG + lane) * 2]];
    if (lane < DEG - 32) s += ftraf[p2l[(l * DEG + 32 + lane) * 2]];
    #pragma unroll
    for (int off = 16; off; off >>= 1) s += __shfl_xor_sync(FULL, s, off);

    float c = cap[l];
    float in0 = c * 1e-5f;
    float in1 = s / (c * 1e9f);

    float ha = fmaxf(0.f, s_b1[d0] + in0 * s_w1[d0] + in1 * s_w1[DD + d0]);
    float hb = fmaxf(0.f, s_b1[d1] + in0 * s_w1[d1] + in1 * s_w1[DD + d1]);

    float oa = s_b2[d0], ob = s_b2[d1];
    #pragma unroll 8
    for (int kk = 0; kk < 32; kk++) {
        float ka = __shfl_sync(FULL, ha, kk);
        float kb = __shfl_sync(FULL, hb, kk);
        float2 wA = *(const float2*)&s_w2[(2 * kk) * DD + d0];
        float2 wB = *(const float2*)&s_w2[(2 * kk + 1) * DD + d0];
        oa += ka * wA.x + kb * wB.x;
        ob += ka * wA.y + kb * wB.y;
    }
    g_link_state[l * DD + d0] = fmaxf(0.f, oa);
    g_link_state[l * DD + d1] = fmaxf(0.f, ob);
}

// ============================================================
// Prepack pg_wh into split-bf16 m16n8k16 B-fragment order.
// ============================================================
__global__ void prepack_wh_kernel(const float* __restrict__ wh)
{
    int i = blockIdx.x * 256 + threadIdx.x;
    if (i >= 4 * 24 * 32) return;
    int lane = i & 31;
    int nt = (i >> 5) % 24;
    int kt = i / (32 * 24);
    int q = lane & 3, g = lane >> 2;
    int n = nt * 8 + g;
    int k0 = kt * 16 + 2 * q;

    float2 f0 = make_float2(wh[k0 * 192 + n],       wh[(k0 + 1) * 192 + n]);
    float2 f1 = make_float2(wh[(k0 + 8) * 192 + n], wh[(k0 + 9) * 192 + n]);
    uint32_t b0h, b0l, b1h, b1l;
    split2(f0.x, f0.y, b0h, b0l);
    split2(f1.x, f1.y, b1h, b1l);
    g_Bpack[i] = make_uint4(b0h, b1h, b0l, b1l);
}

// ============================================================
// link_proj = link_state @ pg_wx + pg_bx (+ pg_bh folded for z/r)
// warp = 5 links -> 250 CTAs (single wave at 2 CTAs/SM)
// ============================================================
#define HALF_SMEM_BYTES ((DD * 192 + 192) * 4)

__global__ void __launch_bounds__(256, 2)
link_proj_kernel(const float* __restrict__ wx_g, const float* __restrict__ bx_g,
                 const float* __restrict__ bh_g)
{
    extern __shared__ float sm[];
    float* s_wx = sm;
    float* s_bx = sm + DD * 192;
    for (int i = threadIdx.x; i < DD * 192; i += 256) s_wx[i] = wx_g[i];
    if (threadIdx.x < 192)
        s_bx[threadIdx.x] = bx_g[threadIdx.x] +
                            (threadIdx.x < 128 ? bh_g[threadIdx.x] : 0.f);
    __syncthreads();

    int warp = threadIdx.x >> 5, lane = threadIdx.x & 31;
    int d0 = 2 * lane;
    int l0 = blockIdx.x * 40 + warp * 5;

    float h0[5], h1[5];
    #pragma unroll
    for (int b = 0; b < 5; b++) {
        int l = l0 + b;
        h0[b] = h1[b] = 0.f;
        if (l < NL) {
            float2 h = *(const float2*)&g_link_state[l * DD + d0];
            h0[b] = h.x; h1[b] = h.y;
        }
    }

    float pz0[5], pz1[5], pr0[5], pr1[5], ph0[5], ph1[5];
    #pragma unroll
    for (int b = 0; b < 5; b++) {
        pz0[b] = s_bx[d0];        pz1[b] = s_bx[d0 + 1];
        pr0[b] = s_bx[64 + d0];   pr1[b] = s_bx[64 + d0 + 1];
        ph0[b] = s_bx[128 + d0];  ph1[b] = s_bx[128 + d0 + 1];
    }
    #pragma unroll 4
    for (int kk = 0; kk < 32; kk++) {
        const float* wa = s_wx + (2 * kk) * 192;
        float2 za = *(const float2*)(wa + d0);
        float2 ra = *(const float2*)(wa + 64 + d0);
        float2 ha = *(const float2*)(wa + 128 + d0);
        float2 zb = *(const float2*)(wa + 192 + d0);
        float2 rb = *(const float2*)(wa + 192 + 64 + d0);
        float2 hb = *(const float2*)(wa + 192 + 128 + d0);
        #pragma unroll
        for (int b = 0; b < 5; b++) {
            float ka = __shfl_sync(FULL, h0[b], kk);
            float kb = __shfl_sync(FULL, h1[b], kk);
            pz0[b] += ka * za.x + kb * zb.x;  pz1[b] += ka * za.y + kb * zb.y;
            pr0[b] += ka * ra.x + kb * rb.x;  pr1[b] += ka * ra.y + kb * rb.y;
            ph0[b] += ka * ha.x + kb * hb.x;  ph1[b] += ka * ha.y + kb * hb.y;
        }
    }
    #pragma unroll
    for (int b = 0; b < 5; b++) {
        int l = l0 + b;
        if (l < NL) {
            *(float2*)&g_link_proj[l * 192 + d0]       = make_float2(pz0[b], pz1[b]);
            *(float2*)&g_link_proj[l * 192 + 64 + d0]  = make_float2(pr0[b], pr1[b]);
            *(float2*)&g_link_proj[l * 192 + 128 + d0] = make_float2(ph0[b], ph1[b]);
        }
    }
}

// ============================================================
// Path GRU via split-bf16 m16n8k16 mma. CTA = 128 paths, 8 warps.
// N processed in TWO 32-column halves per step: C = [12][4] = 48
// regs (fits the 128-reg budget at 2 CTAs/SM -> no spills).
// Half-0's new h is stashed in registers and committed to the
// warp-private A smem arrays only after half-1's MMAs consume
// the old h.
// ============================================================
#define PSM_A_HI  49152
#define PSM_A_LO  (PSM_A_HI + MCTA * ASTR * 4)
#define PSM_BHH   (PSM_A_LO + MCTA * ASTR * 4)
#define MMA_SMEM_BYTES (PSM_BHH + 64 * 4)

__global__ void __launch_bounds__(256, 2)
path_update_mma_kernel(const int* __restrict__ l2p, const float* __restrict__ bh_g, int first)
{
    extern __shared__ unsigned char smraw[];
    uint4*    s_B   = (uint4*)smraw;                      // 3072 uint4 = 48 KB
    uint32_t* s_Ahi = (uint32_t*)(smraw + PSM_A_HI);      // 128 x ASTR
    uint32_t* s_Alo = (uint32_t*)(smraw + PSM_A_LO);
    float*    s_bhh = (float*)(smraw + PSM_BHH);          // 64

    int tid = threadIdx.x;
    #pragma unroll
    for (int i = 0; i < 12; i++) s_B[tid + i * 256] = g_Bpack[tid + i * 256];
    if (tid < 64) s_bhh[tid] = bh_g[128 + tid];

    // prologue: load h rows (fp32), split to bf16x2 hi/lo arrays.
    int pbase = blockIdx.x * MCTA;
    {
        int r = tid >> 1, hf = tid & 1;
        int p = pbase + r;
        int pc = p < NP ? p : NP - 1;
        const float* hsrc = (first ? &g_path_state[(size_t)pc * 64]
                                   : &g_psseq[((size_t)pc * 8 + 7) * 64]) + hf * 32;
        uint32_t* ah = &s_Ahi[r * ASTR + hf * 16];
        uint32_t* al = &s_Alo[r * ASTR + hf * 16];
        #pragma unroll
        for (int j = 0; j < 8; j++) {
            float4 v = *(const float4*)&hsrc[4 * j];
            uint32_t h0, l0, h1, l1;
            split2(v.x, v.y, h0, l0);
            split2(v.z, v.w, h1, l1);
            ah[2 * j] = h0; ah[2 * j + 1] = h1;
            al[2 * j] = l0; al[2 * j + 1] = l1;
        }
    }
    __syncthreads();

    int lane = tid & 31, warp = tid >> 5;
    int q = lane & 3, g = lane >> 2;
    int r0 = warp * 16 + g;                 // local rows r0, r0+8
    int p0 = pbase + r0, p1 = p0 + 8;
    int p0c = (p0 < NP) ? p0 : 0;
    int p1c = (p1 < NP) ? p1 : 0;

    uint32_t* A0hi = &s_Ahi[r0 * ASTR];
    uint32_t* A1hi = &s_Ahi[(r0 + 8) * ASTR];
    uint32_t* A0lo = &s_Alo[r0 * ASTR];
    uint32_t* A1lo = &s_Alo[(r0 + 8) * ASTR];

    for (int t = 0; t < LSEQ; t++) {
        int li0 = l2p[p0c * LSEQ + t];
        int li1 = l2p[p1c * LSEQ + t];
        const float* pr0 = &g_link_proj[li0 * 192];
        const float* pr1 = &g_link_proj[li1 * 192];

        uint32_t st_h[8], st_l[8];   // half-0 new-h stash (committed after half-1)

        #pragma unroll
        for (int hf2 = 0; hf2 < 2; hf2++) {
            float C[12][4];

            // C init: z tiles (c 0..3), r tiles (c 4..7) <- gathered
            // x-projection (biases pre-folded); hh tiles (c 8..11) <- 0.
            #pragma unroll
            for (int c = 0; c < 4; c++) {
                int col = (4 * hf2 + c) * 8 + 2 * q;
                float2 x0 = *(const float2*)&pr0[col];
                float2 x1 = *(const float2*)&pr1[col];
                C[c][0] = x0.x; C[c][1] = x0.y; C[c][2] = x1.x; C[c][3] = x1.y;
            }
            #pragma unroll
            for (int c = 0; c < 4; c++) {
                int col = (8 + 4 * hf2 + c) * 8 + 2 * q;
                float2 x0 = *(const float2*)&pr0[col];
                float2 x1 = *(const float2*)&pr1[col];
                C[4 + c][0] = x0.x; C[4 + c][1] = x0.y; C[4 + c][2] = x1.x; C[4 + c][3] = x1.y;
            }
            #pragma unroll
            for (int c = 8; c < 12; c++) {
                C[c][0] = 0.f; C[c][1] = 0.f; C[c][2] = 0.f; C[c][3] = 0.f;
            }

            // h @ Wh via split-bf16 (old h — untouched until both halves done)
            #pragma unroll
            for (int kt = 0; kt < 4; kt++) {
                int kp = kt * 8 + q;
                uint32_t a0h = A0hi[kp],     a1h = A1hi[kp];
                uint32_t a2h = A0hi[kp + 4], a3h = A1hi[kp + 4];
                uint32_t a0l = A0lo[kp],     a1l = A1lo[kp];
                uint32_t a2l = A0lo[kp + 4], a3l = A1lo[kp + 4];
                const uint4* Bk = s_B + kt * 24 * 32 + lane;
                #pragma unroll
                for (int c = 0; c < 12; c++) {
                    int gnt = (c < 4) ? (4 * hf2 + c)
                            : (c < 8) ? (8 + 4 * hf2 + c - 4)
                                      : (16 + 4 * hf2 + c - 8);
                    uint4 B = Bk[gnt * 32];
                    MMA_BF16(C[c], a0h, a1h, a2h, a3h, B.x, B.y);
                    MMA_BF16(C[c], a0h, a1h, a2h, a3h, B.z, B.w);
                    MMA_BF16(C[c], a0l, a1l, a2l, a3l, B.x, B.y);
                }
            }

            // half-epilogue: 4 column groups of 8 within this 32-col half
            #pragma unroll
            for (int j = 0; j < 4; j++) {
                int col = 32 * hf2 + 8 * j + 2 * q;    // global col 0..63
                int kp  = 16 * hf2 + 4 * j + q;        // h pair index
                float2 xh0 = *(const float2*)&pr0[128 + col];
                float2 xh1 = *(const float2*)&pr1[128 + col];
                float2 bhh = *(const float2*)&s_bhh[col];
                uint32_t ohi0 = A0hi[kp], ohi1 = A1hi[kp];
                uint32_t olo0 = A0lo[kp], olo1 = A1lo[kp];
                float ho00 = __uint_as_float(ohi0 << 16)         + __uint_as_float(olo0 << 16);
                float ho01 = __uint_as_float(ohi0 & 0xffff0000u) + __uint_as_float(olo0 & 0xffff0000u);
                float ho10 = __uint_as_float(ohi1 << 16)         + __uint_as_float(olo1 << 16);
                float ho11 = __uint_as_float(ohi1 & 0xffff0000u) + __uint_as_float(olo1 & 0xffff0000u);

                float n00 = gru_one(C[j][0], C[4 + j][0], C[8 + j][0] + bhh.x, xh0.x, ho00);
                float n01 = gru_one(C[j][1], C[4 + j][1], C[8 + j][1] + bhh.y, xh0.y, ho01);
                float n10 = gru_one(C[j][2], C[4 + j][2], C[8 + j][2] + bhh.x, xh1.x, ho10);
                float n11 = gru_one(C[j][3], C[4 + j][3], C[8 + j][3] + bhh.y, xh1.y, ho11);

                if (p0 < NP) *(float2*)&g_psseq[((size_t)p0 * 8 + t) * 64 + col] = make_float2(n00, n01);
                if (p1 < NP) *(float2*)&g_psseq[((size_t)p1 * 8 + t) * 64 + col] = make_float2(n10, n11);

                uint32_t nh0, nl0, nh1, nl1;
                split2(n00, n01, nh0, nl0);
                split2(n10, n11, nh1, nl1);
                if (hf2 == 0) {
                    st_h[2 * j] = nh0; st_h[2 * j + 1] = nh1;
                    st_l[2 * j] = nl0; st_l[2 * j + 1] = nl1;
                } else {
                    A0hi[kp] = nh0; A1hi[kp] = nh1;
                    A0lo[kp] = nl0; A1lo[kp] = nl1;
                }
            }
        }

        // commit half-0's new h (its MMcolumn consumers are done)
        #pragma unroll
        for (int j = 0; j < 4; j++) {
            int kp = 4 * j + q;
            A0hi[kp] = st_h[2 * j]; A1hi[kp] = st_h[2 * j + 1];
            A0lo[kp] = st_l[2 * j]; A1lo[kp] = st_l[2 * j + 1];
        }
        __syncwarp();   // warp-private rows: order smem h writes before next step's reads
    }
}

// ============================================================
// Gather-sum: path_sum[l] = sum over DEG entries of psseq rows.
// ============================================================
__global__ void __launch_bounds__(256)
gather_sum_kernel(const int* __restrict__ p2l)
{
    __shared__ int2 s_idx[4 * DEG];
    int lbase = blockIdx.x * 4;
    for (int i = threadIdx.x; i < 4 * DEG; i += 256) {
        int ll = lbase + i / DEG;
        if (ll < NL) s_idx[i] = ((const int2*)p2l)[ll * DEG + (i % DEG)];
    }
    __syncthreads();

    int sub = threadIdx.x >> 6;
    int d   = threadIdx.x & 63;
    int l = lbase + sub;
    if (l >= NL) return;

    float s = 0.f;
    #pragma unroll 8
    for (int e = 0; e < DEG; e++) {
        int2 pe = s_idx[sub * DEG + e];
        s += g_psseq[((size_t)pe.x * 8 + (pe.y - 1)) * DD + d];
    }
    g_path_sum[l * DD + d] = s;
}

// ============================================================
// Link GRU on precomputed path_sum. warp = 5 links -> 250 CTAs.
// ============================================================
#define GRU_SMEM_BYTES ((2 * DD * 192 + 2 * 192) * 4)

__global__ void __launch_bounds__(256, 2)
link_gru_kernel(const float* __restrict__ wx_g, const float* __restrict__ wh_g,
                const float* __restrict__ bx_g, const float* __restrict__ bh_g)
{
    extern __shared__ float sm[];
    float* s_wx = sm;
    float* s_wh = sm + DD * 192;
    float* s_bx = s_wh + DD * 192;
    float* s_bh = s_bx + 192;
    for (int i = threadIdx.x; i < DD * 192; i += 256) { s_wx[i] = wx_g[i]; s_wh[i] = wh_g[i]; }
    if (threadIdx.x < 192) { s_bx[threadIdx.x] = bx_g[threadIdx.x]; s_bh[threadIdx.x] = bh_g[threadIdx.x]; }
    __syncthreads();

    int warp = threadIdx.x >> 5, lane = threadIdx.x & 31;
    int d0 = 2 * lane;
    int l0 = blockIdx.x * 40 + warp * 5;

    float h0[5], h1[5], x0[5], x1[5];
    #pragma unroll
    for (int b = 0; b < 5; b++) {
        int l = l0 + b;
        h0[b] = h1[b] = x0[b] = x1[b] = 0.f;
        if (l < NL) {
            float2 h = *(const float2*)&g_link_state[l * DD + d0];
            float2 x = *(const float2*)&g_path_sum[l * DD + d0];
            h0[b] = h.x; h1[b] = h.y; x0[b] = x.x; x1[b] = x.y;
        }
    }

    float bz0 = s_bx[d0] + s_bh[d0],               bz1 = s_bx[d0 + 1] + s_bh[d0 + 1];
    float br0 = s_bx[64 + d0] + s_bh[64 + d0],     br1 = s_bx[64 + d0 + 1] + s_bh[64 + d0 + 1];
    float bxh0 = s_bx[128 + d0],  bxh1 = s_bx[128 + d0 + 1];
    float bhh0 = s_bh[128 + d0],  bhh1 = s_bh[128 + d0 + 1];

    float az0[5], az1[5], ar0[5], ar1[5], ax0[5], ax1[5], ah0[5], ah1[5];
    #pragma unroll
    for (int b = 0; b < 5; b++) {
        az0[b] = bz0;  az1[b] = bz1;  ar0[b] = br0;  ar1[b] = br1;
        ax0[b] = bxh0; ax1[b] = bxh1; ah0[b] = bhh0; ah1[b] = bhh1;
    }
    #pragma unroll 2
    for (int kk = 0; kk < 32; kk++) {
        const float* wxa = s_wx + (2 * kk) * 192;
        const float* wha = s_wh + (2 * kk) * 192;
        float2 xza = *(const float2*)(wxa + d0);
        float2 xra = *(const float2*)(wxa + 64 + d0);
        float2 xha = *(const float2*)(wxa + 128 + d0);
        float2 xzb = *(const float2*)(wxa + 192 + d0);
        float2 xrb = *(const float2*)(wxa + 192 + 64 + d0);
        float2 xhb = *(const float2*)(wxa + 192 + 128 + d0);
        float2 hza = *(const float2*)(wha + d0);
        float2 hra = *(const float2*)(wha + 64 + d0);
        float2 hha = *(const float2*)(wha + 128 + d0);
        float2 hzb = *(const float2*)(wha + 192 + d0);
        float2 hrb = *(const float2*)(wha + 192 + 64 + d0);
        float2 hhb = *(const float2*)(wha + 192 + 128 + d0);
        #pragma unroll
        for (int b = 0; b < 5; b++) {
            float xka = __shfl_sync(FULL, x0[b], kk);
            float xkb = __shfl_sync(FULL, x1[b], kk);
            float hka = __shfl_sync(FULL, h0[b], kk);
            float hkb = __shfl_sync(FULL, h1[b], kk);
            az0[b] += xka * xza.x + xkb * xzb.x + hka * hza.x + hkb * hzb.x;
            az1[b] += xka * xza.y + xkb * xzb.y + hka * hza.y + hkb * hzb.y;
            ar0[b] += xka * xra.x + xkb * xrb.x + hka * hra.x + hkb * hrb.x;
            ar1[b] += xka * xra.y + xkb * xrb.y + hka * hra.y + hkb * hrb.y;
            ax0[b] += xka * xha.x + xkb * xhb.x;
            ax1[b] += xka * xha.y + xkb * xhb.y;
            ah0[b] += hka * hha.x + hkb * hhb.x;
            ah1[b] += hka * hha.y + hkb * hhb.y;
        }
    }
    #pragma unroll
    for (int b = 0; b < 5; b++) {
        int l = l0 + b;
        if (l < NL) {
            float z0 = sigmoidf_(az0[b]), z1 = sigmoidf_(az1[b]);
            float r0 = sigmoidf_(ar0[b]), r1 = sigmoidf_(ar1[b]);
            float g0 = tanhf(ax0[b] + r0 * ah0[b]);
            float g1 = tanhf(ax1[b] + r1 * ah1[b]);
            float n0 = z0 * h0[b] + (1.f - z0) * g0;
            float n1 = z1 * h1[b] + (1.f - z1) * g1;
            *(float2*)&g_link_state[l * DD + d0] = make_float2(n0, n1);
        }
    }
}

// ============================================================
// Readout
// ============================================================
__global__ void readout_kernel(const int* __restrict__ l2p, const float* __restrict__ cap,
                               const float* __restrict__ w1, const float* __restrict__ b1,
                               const float* __restrict__ w2, const float* __restrict__ b2,
                               const float* __restrict__ w3, const float* __restrict__ b3,
                               float* __restrict__ out)
{
    __shared__ float s_w1[DD * 32];
    __shared__ float s_w2[32 * 16];
    __shared__ float s_w3[16];
    __shared__ float s_b1[32];
    __shared__ float s_b2[16];
    __shared__ float s_b3;
    for (int i = threadIdx.x; i < DD * 32; i += blockDim.x) s_w1[i] = w1[i];
    for (int i = threadIdx.x; i < 32 * 16; i += blockDim.x) s_w2[i] = w2[i];
    if (threadIdx.x < 16) { s_w3[threadIdx.x] = w3[threadIdx.x]; s_b2[threadIdx.x] = b2[threadIdx.x]; }
    if (threadIdx.x < 32) s_b1[threadIdx.x] = b1[threadIdx.x];
    if (threadIdx.x == 0) s_b3 = b3[0];
    __syncthreads();

    int warp = threadIdx.x >> 5, lane = threadIdx.x & 31;
    int p = blockIdx.x * 8 + warp;
    if (p >= NP) return;
    int d0 = 2 * lane;

    float delay = 0.f;
    for (int t = 0; t < LSEQ; t++) {
        float2 in = *(const float2*)&g_psseq[((size_t)p * 8 + t) * DD + d0];
        float a = s_b1[lane];
        #pragma unroll 8
        for (int kk = 0; kk < 32; kk++) {
            float ka = __shfl_sync(FULL, in.x, kk);
            float kb = __shfl_sync(FULL, in.y, kk);
            a += ka * s_w1[(2 * kk) * 32 + lane] + kb * s_w1[(2 * kk + 1) * 32 + lane];
        }
        a = fmaxf(a, 0.f);
        float c = s_b2[lane & 15];
        #pragma unroll 8
        for (int k = 0; k < 32; k++) {
            float hk = __shfl_sync(FULL, a, k);
            c += hk * s_w2[k * 16 + (lane & 15)];
        }
        c = fmaxf(c, 0.f);
        float term = (lane < 16) ? c * s_w3[lane] : 0.f;
        #pragma unroll
        for (int off = 16; off; off >>= 1) term += __shfl_xor_sync(FULL, term, off);
        float xo = term + s_b3;
        float occ = fmaxf(xo, 0.f) + log1pf(expf(-fabsf(xo)));
        int li = l2p[p * LSEQ + t];
        delay += occ / cap[li];
    }
    if (lane == 0) out[p] = delay;
}

// ============================================================
// Launch
// ============================================================
extern "C" void kernel_launch(void* const* d_in, const int* in_sizes, int n_in,
                              void* d_out, int out_size)
{
    const float* ft    = (const float*)d_in[0];
    const float* fpk   = (const float*)d_in[1];
    const float* fps   = (const float*)d_in[2];
    const float* cap   = (const float*)d_in[3];
    const int*   l2p   = (const int*)d_in[4];
    const int*   p2l   = (const int*)d_in[5];
    const float* pe_w1 = (const float*)d_in[6],  *pe_b1 = (const float*)d_in[7];
    const float* pe_w2 = (const float*)d_in[8],  *pe_b2 = (const float*)d_in[9];
    const float* le_w1 = (const float*)d_in[10], *le_b1 = (const float*)d_in[11];
    const float* le_w2 = (const float*)d_in[12], *le_b2 = (const float*)d_in[13];
    const float* pg_wx = (const float*)d_in[14], *pg_wh = (const float*)d_in[15];
    const float* pg_bx = (const float*)d_in[16], *pg_bh = (const float*)d_in[17];
    const float* lg_wx = (const float*)d_in[18], *lg_wh = (const float*)d_in[19];
    const float* lg_bx = (const float*)d_in[20], *lg_bh = (const float*)d_in[21];
    const float* ro_w1 = (const float*)d_in[22], *ro_b1 = (const float*)d_in[23];
    const float* ro_w2 = (const float*)d_in[24], *ro_b2 = (const float*)d_in[25];
    const float* ro_w3 = (const float*)d_in[26], *ro_b3 = (const float*)d_in[27];

    cudaFuncSetAttribute(link_proj_kernel,       cudaFuncAttributeMaxDynamicSharedMemorySize, HALF_SMEM_BYTES);
    cudaFuncSetAttribute(path_update_mma_kernel, cudaFuncAttributeMaxDynamicSharedMemorySize, MMA_SMEM_BYTES);
    cudaFuncSetAttribute(link_gru_kernel,        cudaFuncAttributeMaxDynamicSharedMemorySize, GRU_SMEM_BYTES);

    path_embed_kernel<<<(NP + 7) / 8, 256>>>(ft, fpk, fps, pe_w1, pe_b1, pe_w2, pe_b2);
    link_embed_kernel<<<(NL + 7) / 8, 256>>>(ft, cap, p2l, le_w1, le_b1, le_w2, le_b2);
    prepack_wh_kernel<<<(4 * 24 * 32 + 255) / 256, 256>>>(pg_wh);

    for (int it = 0; it < 8; it++) {
        link_proj_kernel<<<(NL + 39) / 40, 256, HALF_SMEM_BYTES>>>(pg_wx, pg_bx, pg_bh);
        path_update_mma_kernel<<<(NP + MCTA - 1) / MCTA, 256, MMA_SMEM_BYTES>>>(
            l2p, pg_bh, it == 0 ? 1 : 0);
        gather_sum_kernel<<<(NL + 3) / 4, 256>>>(p2l);
        link_gru_kernel<<<(NL + 39) / 40, 256, GRU_SMEM_BYTES>>>(
            lg_wx, lg_wh, lg_bx, lg_bh);
    }

    readout_kernel<<<(NP + 7) / 8, 256>>>(l2p, cap, ro_w1, ro_b1, ro_w2, ro_b2, ro_w3, ro_b3,
                                          (float*)d_out);
}

// round 11
// speedup vs baseline: 1.1608x; 1.0334x over previous
#include <cuda_runtime.h>
#include <math.h>
#include <stdint.h>

#define NP   50000
#define NL   10000
#define LSEQ 8
#define DEG  40
#define DD   64
#define FULL 0xffffffffu
#define MCTA 64           // paths per CTA in mma path kernel (wave-balance: 782 CTAs / 444 slots)
#define ASTR 36           // u32 row stride of split-h arrays (bank-conflict-free)

// ---- persistent scratch (device globals: allocation-free) ----
__device__ float g_path_state[NP * DD];
__device__ float g_link_state[NL * DD];
__device__ float g_link_proj[NL * 192];              // x-proj with z/r biases folded in
__device__ float g_path_sum[NL * DD];
__device__ float g_psseq[(size_t)NP * 8 * DD];       // slots = steps 1..8
__device__ uint4 g_Bpack[4 * 24 * 32];               // Wh split-bf16 fragment pack (48KB)

__device__ __forceinline__ float sigmoidf_(float x) { return 1.0f / (1.0f + expf(-x)); }

__device__ __forceinline__ float fast_ex2(float x) {
    float r; asm("ex2.approx.f32 %0, %1;" : "=f"(r) : "f"(x)); return r;
}
__device__ __forceinline__ float fast_rcp(float x) {
    float r; asm("rcp.approx.f32 %0, %1;" : "=f"(r) : "f"(x)); return r;
}
__device__ __forceinline__ float fsig(float x) {
    return fast_rcp(1.f + fast_ex2(-1.4426950408889634f * x));
}
__device__ __forceinline__ float ftanh(float x) {
    return 1.f - 2.f * fast_rcp(1.f + fast_ex2(2.8853900817779268f * x));
}
__device__ __forceinline__ float gru_one(float zp, float rp, float hp, float xh, float ho) {
    float z = fsig(zp), r = fsig(rp);
    float gg = ftanh(xh + r * hp);
    return z * ho + (1.f - z) * gg;
}

// pack lo->lower16, hi->upper16 bf16x2
__device__ __forceinline__ uint32_t pack_bf16x2(float lo, float hi) {
    uint32_t r; asm("cvt.rn.bf16x2.f32 %0, %1, %2;" : "=r"(r) : "f"(hi), "f"(lo)); return r;
}
__device__ __forceinline__ void split2(float a, float b, uint32_t& hi, uint32_t& lo) {
    hi = pack_bf16x2(a, b);
    float ra = a - __uint_as_float(hi << 16);
    float rb = b - __uint_as_float(hi & 0xffff0000u);
    lo = pack_bf16x2(ra, rb);
}

#define MMA_BF16(c, a0, a1, a2, a3, b0, b1)                                   \
    asm("mma.sync.aligned.m16n8k16.row.col.f32.bf16.bf16.f32 "                \
        "{%0,%1,%2,%3}, {%4,%5,%6,%7}, {%8,%9}, {%0,%1,%2,%3};"               \
        : "+f"((c)[0]), "+f"((c)[1]), "+f"((c)[2]), "+f"((c)[3])              \
        : "r"(a0), "r"(a1), "r"(a2), "r"(a3), "r"(b0), "r"(b1))

// ============================================================
// Path embedding: 3 -> 64 -> 64 MLP (relu), warp per path
// ============================================================
__global__ void path_embed_kernel(const float* __restrict__ ft, const float* __restrict__ fp,
                                  const float* __restrict__ fps,
                                  const float* __restrict__ w1, const float* __restrict__ b1,
                                  const float* __restrict__ w2, const float* __restrict__ b2)
{
    __shared__ float s_w2[DD * DD];
    __shared__ float s_w1[3 * DD];
    __shared__ float s_b1[DD];
    __shared__ float s_b2[DD];
    for (int i = threadIdx.x; i < DD * DD; i += blockDim.x) s_w2[i] = w2[i];
    for (int i = threadIdx.x; i < 3 * DD; i += blockDim.x) s_w1[i] = w1[i];
    for (int i = threadIdx.x; i < DD; i += blockDim.x) { s_b1[i] = b1[i]; s_b2[i] = b2[i]; }
    __syncthreads();

    int warp = threadIdx.x >> 5, lane = threadIdx.x & 31;
    int p = blockIdx.x * 8 + warp;
    if (p >= NP) return;
    int d0 = 2 * lane, d1 = d0 + 1;

    float in0 = ft[p] * 1e-4f;
    float in1 = fp[p] * 1e-3f;
    float in2 = fps[p] * 1e-3f;

    float ha = fmaxf(0.f, s_b1[d0] + in0 * s_w1[d0] + in1 * s_w1[DD + d0] + in2 * s_w1[2 * DD + d0]);
    float hb = fmaxf(0.f, s_b1[d1] + in0 * s_w1[d1] + in1 * s_w1[DD + d1] + in2 * s_w1[2 * DD + d1]);

    float oa = s_b2[d0], ob = s_b2[d1];
    #pragma unroll 8
    for (int kk = 0; kk < 32; kk++) {
        float ka = __shfl_sync(FULL, ha, kk);
        float kb = __shfl_sync(FULL, hb, kk);
        float2 wA = *(const float2*)&s_w2[(2 * kk) * DD + d0];
        float2 wB = *(const float2*)&s_w2[(2 * kk + 1) * DD + d0];
        oa += ka * wA.x + kb * wB.x;
        ob += ka * wA.y + kb * wB.y;
    }
    g_path_state[p * DD + d0] = fmaxf(0.f, oa);
    g_path_state[p * DD + d1] = fmaxf(0.f, ob);
}

// ============================================================
// Link embedding
// ============================================================
__global__ void link_embed_kernel(const float* __restrict__ ftraf, const float* __restrict__ cap,
                                  const int* __restrict__ p2l,
                                  const float* __restrict__ w1, const float* __restrict__ b1,
                                  const float* __restrict__ w2, const float* __restrict__ b2)
{
    __shared__ float s_w2[DD * DD];
    __shared__ float s_w1[2 * DD];
    __shared__ float s_b1[DD];
    __shared__ float s_b2[DD];
    for (int i = threadIdx.x; i < DD * DD; i += blockDim.x) s_w2[i] = w2[i];
    for (int i = threadIdx.x; i < 2 * DD; i += blockDim.x) s_w1[i] = w1[i];
    for (int i = threadIdx.x; i < DD; i += blockDim.x) { s_b1[i] = b1[i]; s_b2[i] = b2[i]; }
    __syncthreads();

    int warp = threadIdx.x >> 5, lane = threadIdx.x & 31;
    int l = blockIdx.x * 8 + warp;
    if (l >= NL) return;
    int d0 = 2 * lane, d1 = d0 + 1;

    float s = ftraf[p2l[(l * DEG + lane) * 2]];
    if (lane < DEG - 32) s += ftraf[p2l[(l * DEG + 32 + lane) * 2]];
    #pragma unroll
    for (int off = 16; off; off >>= 1) s += __shfl_xor_sync(FULL, s, off);

    float c = cap[l];
    float in0 = c * 1e-5f;
    float in1 = s / (c * 1e9f);

    float ha = fmaxf(0.f, s_b1[d0] + in0 * s_w1[d0] + in1 * s_w1[DD + d0]);
    float hb = fmaxf(0.f, s_b1[d1] + in0 * s_w1[d1] + in1 * s_w1[DD + d1]);

    float oa = s_b2[d0], ob = s_b2[d1];
    #pragma unroll 8
    for (int kk = 0; kk < 32; kk++) {
        float ka = __shfl_sync(FULL, ha, kk);
        float kb = __shfl_sync(FULL, hb, kk);
        float2 wA = *(const float2*)&s_w2[(2 * kk) * DD + d0];
        float2 wB = *(const float2*)&s_w2[(2 * kk + 1) * DD + d0];
        oa += ka * wA.x + kb * wB.x;
        ob += ka * wA.y + kb * wB.y;
    }
    g_link_state[l * DD + d0] = fmaxf(0.f, oa);
    g_link_state[l * DD + d1] = fmaxf(0.f, ob);
}

// ============================================================
// Prepack pg_wh into split-bf16 m16n8k16 B-fragment order.
// ============================================================
__global__ void prepack_wh_kernel(const float* __restrict__ wh)
{
    int i = blockIdx.x * 256 + threadIdx.x;
    if (i >= 4 * 24 * 32) return;
    int lane = i & 31;
    int nt = (i >> 5) % 24;
    int kt = i / (32 * 24);
    int q = lane & 3, g = lane >> 2;
    int n = nt * 8 + g;
    int k0 = kt * 16 + 2 * q;

    float2 f0 = make_float2(wh[k0 * 192 + n],       wh[(k0 + 1) * 192 + n]);
    float2 f1 = make_float2(wh[(k0 + 8) * 192 + n], wh[(k0 + 9) * 192 + n]);
    uint32_t b0h, b0l, b1h, b1l;
    split2(f0.x, f0.y, b0h, b0l);
    split2(f1.x, f1.y, b1h, b1l);
    g_Bpack[i] = make_uint4(b0h, b1h, b0l, b1l);
}

// ============================================================
// link_proj = link_state @ pg_wx + pg_bx (+ pg_bh folded for z/r)
// warp = 5 links -> 250 CTAs (single wave at 2 CTAs/SM)
// ============================================================
#define HALF_SMEM_BYTES ((DD * 192 + 192) * 4)

__global__ void __launch_bounds__(256, 2)
link_proj_kernel(const float* __restrict__ wx_g, const float* __restrict__ bx_g,
                 const float* __restrict__ bh_g)
{
    extern __shared__ float sm[];
    float* s_wx = sm;
    float* s_bx = sm + DD * 192;
    for (int i = threadIdx.x; i < DD * 192; i += 256) s_wx[i] = wx_g[i];
    if (threadIdx.x < 192)
        s_bx[threadIdx.x] = bx_g[threadIdx.x] +
                            (threadIdx.x < 128 ? bh_g[threadIdx.x] : 0.f);
    __syncthreads();

    int warp = threadIdx.x >> 5, lane = threadIdx.x & 31;
    int d0 = 2 * lane;
    int l0 = blockIdx.x * 40 + warp * 5;

    float h0[5], h1[5];
    #pragma unroll
    for (int b = 0; b < 5; b++) {
        int l = l0 + b;
        h0[b] = h1[b] = 0.f;
        if (l < NL) {
            float2 h = *(const float2*)&g_link_state[l * DD + d0];
            h0[b] = h.x; h1[b] = h.y;
        }
    }

    float pz0[5], pz1[5], pr0[5], pr1[5], ph0[5], ph1[5];
    #pragma unroll
    for (int b = 0; b < 5; b++) {
        pz0[b] = s_bx[d0];        pz1[b] = s_bx[d0 + 1];
        pr0[b] = s_bx[64 + d0];   pr1[b] = s_bx[64 + d0 + 1];
        ph0[b] = s_bx[128 + d0];  ph1[b] = s_bx[128 + d0 + 1];
    }
    #pragma unroll 4
    for (int kk = 0; kk < 32; kk++) {
        const float* wa = s_wx + (2 * kk) * 192;
        float2 za = *(const float2*)(wa + d0);
        float2 ra = *(const float2*)(wa + 64 + d0);
        float2 ha = *(const float2*)(wa + 128 + d0);
        float2 zb = *(const float2*)(wa + 192 + d0);
        float2 rb = *(const float2*)(wa + 192 + 64 + d0);
        float2 hb = *(const float2*)(wa + 192 + 128 + d0);
        #pragma unroll
        for (int b = 0; b < 5; b++) {
            float ka = __shfl_sync(FULL, h0[b], kk);
            float kb = __shfl_sync(FULL, h1[b], kk);
            pz0[b] += ka * za.x + kb * zb.x;  pz1[b] += ka * za.y + kb * zb.y;
            pr0[b] += ka * ra.x + kb * rb.x;  pr1[b] += ka * ra.y + kb * rb.y;
            ph0[b] += ka * ha.x + kb * hb.x;  ph1[b] += ka * ha.y + kb * hb.y;
        }
    }
    #pragma unroll
    for (int b = 0; b < 5; b++) {
        int l = l0 + b;
        if (l < NL) {
            *(float2*)&g_link_proj[l * 192 + d0]       = make_float2(pz0[b], pz1[b]);
            *(float2*)&g_link_proj[l * 192 + 64 + d0]  = make_float2(pr0[b], pr1[b]);
            *(float2*)&g_link_proj[l * 192 + 128 + d0] = make_float2(ph0[b], ph1[b]);
        }
    }
}

// ============================================================
// Path GRU via split-bf16 m16n8k16 mma. CTA = 64 paths, 4 warps,
// 3 CTAs/SM (782 CTAs over 444 slots -> balanced waves).
// N processed in TWO 32-column halves per step: C = [12][4].
// Half-0's new h stashed in regs, committed after half-1.
// ============================================================
#define PSM_A_HI  49152
#define PSM_A_LO  (PSM_A_HI + MCTA * ASTR * 4)
#define PSM_BHH   (PSM_A_LO + MCTA * ASTR * 4)
#define MMA_SMEM_BYTES (PSM_BHH + 64 * 4)

__global__ void __launch_bounds__(128, 3)
path_update_mma_kernel(const int* __restrict__ l2p, const float* __restrict__ bh_g, int first)
{
    extern __shared__ unsigned char smraw[];
    uint4*    s_B   = (uint4*)smraw;                      // 3072 uint4 = 48 KB
    uint32_t* s_Ahi = (uint32_t*)(smraw + PSM_A_HI);      // 64 x ASTR
    uint32_t* s_Alo = (uint32_t*)(smraw + PSM_A_LO);
    float*    s_bhh = (float*)(smraw + PSM_BHH);          // 64

    int tid = threadIdx.x;
    #pragma unroll
    for (int i = 0; i < 24; i++) s_B[tid + i * 128] = g_Bpack[tid + i * 128];
    if (tid < 64) s_bhh[tid] = bh_g[128 + tid];

    // prologue: load h rows (fp32), split to bf16x2 hi/lo arrays.
    int pbase = blockIdx.x * MCTA;
    {
        int r = tid >> 1, hf = tid & 1;        // 64 rows x 2 halves
        int p = pbase + r;
        int pc = p < NP ? p : NP - 1;
        const float* hsrc = (first ? &g_path_state[(size_t)pc * 64]
                                   : &g_psseq[((size_t)pc * 8 + 7) * 64]) + hf * 32;
        uint32_t* ah = &s_Ahi[r * ASTR + hf * 16];
        uint32_t* al = &s_Alo[r * ASTR + hf * 16];
        #pragma unroll
        for (int j = 0; j < 8; j++) {
            float4 v = *(const float4*)&hsrc[4 * j];
            uint32_t h0, l0, h1, l1;
            split2(v.x, v.y, h0, l0);
            split2(v.z, v.w, h1, l1);
            ah[2 * j] = h0; ah[2 * j + 1] = h1;
            al[2 * j] = l0; al[2 * j + 1] = l1;
        }
    }
    __syncthreads();

    int lane = tid & 31, warp = tid >> 5;
    int q = lane & 3, g = lane >> 2;
    int r0 = warp * 16 + g;                 // local rows r0, r0+8 (warp 0..3 covers 64)
    int p0 = pbase + r0, p1 = p0 + 8;
    int p0c = (p0 < NP) ? p0 : 0;
    int p1c = (p1 < NP) ? p1 : 0;

    uint32_t* A0hi = &s_Ahi[r0 * ASTR];
    uint32_t* A1hi = &s_Ahi[(r0 + 8) * ASTR];
    uint32_t* A0lo = &s_Alo[r0 * ASTR];
    uint32_t* A1lo = &s_Alo[(r0 + 8) * ASTR];

    for (int t = 0; t < LSEQ; t++) {
        int li0 = l2p[p0c * LSEQ + t];
        int li1 = l2p[p1c * LSEQ + t];
        const float* pr0 = &g_link_proj[li0 * 192];
        const float* pr1 = &g_link_proj[li1 * 192];

        uint32_t st_h[8], st_l[8];   // half-0 new-h stash (committed after half-1)

        #pragma unroll
        for (int hf2 = 0; hf2 < 2; hf2++) {
            float C[12][4];

            // C init: z tiles (c 0..3), r tiles (c 4..7) <- gathered
            // x-projection (biases pre-folded); hh tiles (c 8..11) <- 0.
            #pragma unroll
            for (int c = 0; c < 4; c++) {
                int col = (4 * hf2 + c) * 8 + 2 * q;
                float2 x0 = *(const float2*)&pr0[col];
                float2 x1 = *(const float2*)&pr1[col];
                C[c][0] = x0.x; C[c][1] = x0.y; C[c][2] = x1.x; C[c][3] = x1.y;
            }
            #pragma unroll
            for (int c = 0; c < 4; c++) {
                int col = (8 + 4 * hf2 + c) * 8 + 2 * q;
                float2 x0 = *(const float2*)&pr0[col];
                float2 x1 = *(const float2*)&pr1[col];
                C[4 + c][0] = x0.x; C[4 + c][1] = x0.y; C[4 + c][2] = x1.x; C[4 + c][3] = x1.y;
            }
            #pragma unroll
            for (int c = 8; c < 12; c++) {
                C[c][0] = 0.f; C[c][1] = 0.f; C[c][2] = 0.f; C[c][3] = 0.f;
            }

            // h @ Wh via split-bf16 (old h — untouched until both halves done)
            #pragma unroll
            for (int kt = 0; kt < 4; kt++) {
                int kp = kt * 8 + q;
                uint32_t a0h = A0hi[kp],     a1h = A1hi[kp];
                uint32_t a2h = A0hi[kp + 4], a3h = A1hi[kp + 4];
                uint32_t a0l = A0lo[kp],     a1l = A1lo[kp];
                uint32_t a2l = A0lo[kp + 4], a3l = A1lo[kp + 4];
                const uint4* Bk = s_B + kt * 24 * 32 + lane;
                #pragma unroll
                for (int c = 0; c < 12; c++) {
                    int gnt = (c < 4) ? (4 * hf2 + c)
                            : (c < 8) ? (8 + 4 * hf2 + c - 4)
                                      : (16 + 4 * hf2 + c - 8);
                    uint4 B = Bk[gnt * 32];
                    MMA_BF16(C[c], a0h, a1h, a2h, a3h, B.x, B.y);
                    MMA_BF16(C[c], a0h, a1h, a2h, a3h, B.z, B.w);
                    MMA_BF16(C[c], a0l, a1l, a2l, a3l, B.x, B.y);
                }
            }

            // half-epilogue: 4 column groups of 8 within this 32-col half
            #pragma unroll
            for (int j = 0; j < 4; j++) {
                int col = 32 * hf2 + 8 * j + 2 * q;    // global col 0..63
                int kp  = 16 * hf2 + 4 * j + q;        // h pair index
                float2 xh0 = *(const float2*)&pr0[128 + col];
                float2 xh1 = *(const float2*)&pr1[128 + col];
                float2 bhh = *(const float2*)&s_bhh[col];
                uint32_t ohi0 = A0hi[kp], ohi1 = A1hi[kp];
                uint32_t olo0 = A0lo[kp], olo1 = A1lo[kp];
                float ho00 = __uint_as_float(ohi0 << 16)         + __uint_as_float(olo0 << 16);
                float ho01 = __uint_as_float(ohi0 & 0xffff0000u) + __uint_as_float(olo0 & 0xffff0000u);
                float ho10 = __uint_as_float(ohi1 << 16)         + __uint_as_float(olo1 << 16);
                float ho11 = __uint_as_float(ohi1 & 0xffff0000u) + __uint_as_float(olo1 & 0xffff0000u);

                float n00 = gru_one(C[j][0], C[4 + j][0], C[8 + j][0] + bhh.x, xh0.x, ho00);
                float n01 = gru_one(C[j][1], C[4 + j][1], C[8 + j][1] + bhh.y, xh0.y, ho01);
                float n10 = gru_one(C[j][2], C[4 + j][2], C[8 + j][2] + bhh.x, xh1.x, ho10);
                float n11 = gru_one(C[j][3], C[4 + j][3], C[8 + j][3] + bhh.y, xh1.y, ho11);

                if (p0 < NP) *(float2*)&g_psseq[((size_t)p0 * 8 + t) * 64 + col] = make_float2(n00, n01);
                if (p1 < NP) *(float2*)&g_psseq[((size_t)p1 * 8 + t) * 64 + col] = make_float2(n10, n11);

                uint32_t nh0, nl0, nh1, nl1;
                split2(n00, n01, nh0, nl0);
                split2(n10, n11, nh1, nl1);
                if (hf2 == 0) {
                    st_h[2 * j] = nh0; st_h[2 * j + 1] = nh1;
                    st_l[2 * j] = nl0; st_l[2 * j + 1] = nl1;
                } else {
                    A0hi[kp] = nh0; A1hi[kp] = nh1;
                    A0lo[kp] = nl0; A1lo[kp] = nl1;
                }
            }
        }

        // commit half-0's new h (its MMA consumers are done)
        #pragma unroll
        for (int j = 0; j < 4; j++) {
            int kp = 4 * j + q;
            A0hi[kp] = st_h[2 * j]; A1hi[kp] = st_h[2 * j + 1];
            A0lo[kp] = st_l[2 * j]; A1lo[kp] = st_l[2 * j + 1];
        }
        __syncwarp();   // warp-private rows: order smem h writes before next step's reads
    }
}

// ============================================================
// Gather-sum: path_sum[l] = sum over DEG entries of psseq rows.
// ============================================================
__global__ void __launch_bounds__(256)
gather_sum_kernel(const int* __restrict__ p2l)
{
    __shared__ int2 s_idx[4 * DEG];
    int lbase = blockIdx.x * 4;
    for (int i = threadIdx.x; i < 4 * DEG; i += 256) {
        int ll = lbase + i / DEG;
        if (ll < NL) s_idx[i] = ((const int2*)p2l)[ll * DEG + (i % DEG)];
    }
    __syncthreads();

    int sub = threadIdx.x >> 6;
    int d   = threadIdx.x & 63;
    int l = lbase + sub;
    if (l >= NL) return;

    float s = 0.f;
    #pragma unroll 8
    for (int e = 0; e < DEG; e++) {
        int2 pe = s_idx[sub * DEG + e];
        s += g_psseq[((size_t)pe.x * 8 + (pe.y - 1)) * DD + d];
    }
    g_path_sum[l * DD + d] = s;
}

// ============================================================
// Link GRU on precomputed path_sum. warp = 5 links -> 250 CTAs.
// ============================================================
#define GRU_SMEM_BYTES ((2 * DD * 192 + 2 * 192) * 4)

__global__ void __launch_bounds__(256, 2)
link_gru_kernel(const float* __restrict__ wx_g, const float* __restrict__ wh_g,
                const float* __restrict__ bx_g, const float* __restrict__ bh_g)
{
    extern __shared__ float sm[];
    float* s_wx = sm;
    float* s_wh = sm + DD * 192;
    float* s_bx = s_wh + DD * 192;
    float* s_bh = s_bx + 192;
    for (int i = threadIdx.x; i < DD * 192; i += 256) { s_wx[i] = wx_g[i]; s_wh[i] = wh_g[i]; }
    if (threadIdx.x < 192) { s_bx[threadIdx.x] = bx_g[threadIdx.x]; s_bh[threadIdx.x] = bh_g[threadIdx.x]; }
    __syncthreads();

    int warp = threadIdx.x >> 5, lane = threadIdx.x & 31;
    int d0 = 2 * lane;
    int l0 = blockIdx.x * 40 + warp * 5;

    float h0[5], h1[5], x0[5], x1[5];
    #pragma unroll
    for (int b = 0; b < 5; b++) {
        int l = l0 + b;
        h0[b] = h1[b] = x0[b] = x1[b] = 0.f;
        if (l < NL) {
            float2 h = *(const float2*)&g_link_state[l * DD + d0];
            float2 x = *(const float2*)&g_path_sum[l * DD + d0];
            h0[b] = h.x; h1[b] = h.y; x0[b] = x.x; x1[b] = x.y;
        }
    }

    float bz0 = s_bx[d0] + s_bh[d0],               bz1 = s_bx[d0 + 1] + s_bh[d0 + 1];
    float br0 = s_bx[64 + d0] + s_bh[64 + d0],     br1 = s_bx[64 + d0 + 1] + s_bh[64 + d0 + 1];
    float bxh0 = s_bx[128 + d0],  bxh1 = s_bx[128 + d0 + 1];
    float bhh0 = s_bh[128 + d0],  bhh1 = s_bh[128 + d0 + 1];

    float az0[5], az1[5], ar0[5], ar1[5], ax0[5], ax1[5], ah0[5], ah1[5];
    #pragma unroll
    for (int b = 0; b < 5; b++) {
        az0[b] = bz0;  az1[b] = bz1;  ar0[b] = br0;  ar1[b] = br1;
        ax0[b] = bxh0; ax1[b] = bxh1; ah0[b] = bhh0; ah1[b] = bhh1;
    }
    #pragma unroll 2
    for (int kk = 0; kk < 32; kk++) {
        const float* wxa = s_wx + (2 * kk) * 192;
        const float* wha = s_wh + (2 * kk) * 192;
        float2 xza = *(const float2*)(wxa + d0);
        float2 xra = *(const float2*)(wxa + 64 + d0);
        float2 xha = *(const float2*)(wxa + 128 + d0);
        float2 xzb = *(const float2*)(wxa + 192 + d0);
        float2 xrb = *(const float2*)(wxa + 192 + 64 + d0);
        float2 xhb = *(const float2*)(wxa + 192 + 128 + d0);
        float2 hza = *(const float2*)(wha + d0);
        float2 hra = *(const float2*)(wha + 64 + d0);
        float2 hha = *(const float2*)(wha + 128 + d0);
        float2 hzb = *(const float2*)(wha + 192 + d0);
        float2 hrb = *(const float2*)(wha + 192 + 64 + d0);
        float2 hhb = *(const float2*)(wha + 192 + 128 + d0);
        #pragma unroll
        for (int b = 0; b < 5; b++) {
            float xka = __shfl_sync(FULL, x0[b], kk);
            float xkb = __shfl_sync(FULL, x1[b], kk);
            float hka = __shfl_sync(FULL, h0[b], kk);
            float hkb = __shfl_sync(FULL, h1[b], kk);
            az0[b] += xka * xza.x + xkb * xzb.x + hka * hza.x + hkb * hzb.x;
            az1[b] += xka * xza.y + xkb * xzb.y + hka * hza.y + hkb * hzb.y;
            ar0[b] += xka * xra.x + xkb * xrb.x + hka * hra.x + hkb * hrb.x;
            ar1[b] += xka * xra.y + xkb * xrb.y + hka * hra.y + hkb * hrb.y;
            ax0[b] += xka * xha.x + xkb * xhb.x;
            ax1[b] += xka * xha.y + xkb * xhb.y;
            ah0[b] += hka * hha.x + hkb * hhb.x;
            ah1[b] += hka * hha.y + hkb * hhb.y;
        }
    }
    #pragma unroll
    for (int b = 0; b < 5; b++) {
        int l = l0 + b;
        if (l < NL) {
            float z0 = sigmoidf_(az0[b]), z1 = sigmoidf_(az1[b]);
            float r0 = sigmoidf_(ar0[b]), r1 = sigmoidf_(ar1[b]);
            float g0 = tanhf(ax0[b] + r0 * ah0[b]);
            float g1 = tanhf(ax1[b] + r1 * ah1[b]);
            float n0 = z0 * h0[b] + (1.f - z0) * g0;
            float n1 = z1 * h1[b] + (1.f - z1) * g1;
            *(float2*)&g_link_state[l * DD + d0] = make_float2(n0, n1);
        }
    }
}

// ============================================================
// Readout
// ============================================================
__global__ void readout_kernel(const int* __restrict__ l2p, const float* __restrict__ cap,
                               const float* __restrict__ w1, const float* __restrict__ b1,
                               const float* __restrict__ w2, const float* __restrict__ b2,
                               const float* __restrict__ w3, const float* __restrict__ b3,
                               float* __restrict__ out)
{
    __shared__ float s_w1[DD * 32];
    __shared__ float s_w2[32 * 16];
    __shared__ float s_w3[16];
    __shared__ float s_b1[32];
    __shared__ float s_b2[16];
    __shared__ float s_b3;
    for (int i = threadIdx.x; i < DD * 32; i += blockDim.x) s_w1[i] = w1[i];
    for (int i = threadIdx.x; i < 32 * 16; i += blockDim.x) s_w2[i] = w2[i];
    if (threadIdx.x < 16) { s_w3[threadIdx.x] = w3[threadIdx.x]; s_b2[threadIdx.x] = b2[threadIdx.x]; }
    if (threadIdx.x < 32) s_b1[threadIdx.x] = b1[threadIdx.x];
    if (threadIdx.x == 0) s_b3 = b3[0];
    __syncthreads();

    int warp = threadIdx.x >> 5, lane = threadIdx.x & 31;
    int p = blockIdx.x * 8 + warp;
    if (p >= NP) return;
    int d0 = 2 * lane;

    float delay = 0.f;
    for (int t = 0; t < LSEQ; t++) {
        float2 in = *(const float2*)&g_psseq[((size_t)p * 8 + t) * DD + d0];
        float a = s_b1[lane];
        #pragma unroll 8
        for (int kk = 0; kk < 32; kk++) {
            float ka = __shfl_sync(FULL, in.x, kk);
            float kb = __shfl_sync(FULL, in.y, kk);
            a += ka * s_w1[(2 * kk) * 32 + lane] + kb * s_w1[(2 * kk + 1) * 32 + lane];
        }
        a = fmaxf(a, 0.f);
        float c = s_b2[lane & 15];
        #pragma unroll 8
        for (int k = 0; k < 32; k++) {
            float hk = __shfl_sync(FULL, a, k);
            c += hk * s_w2[k * 16 + (lane & 15)];
        }
        c = fmaxf(c, 0.f);
        float term = (lane < 16) ? c * s_w3[lane] : 0.f;
        #pragma unroll
        for (int off = 16; off; off >>= 1) term += __shfl_xor_sync(FULL, term, off);
        float xo = term + s_b3;
        float occ = fmaxf(xo, 0.f) + log1pf(expf(-fabsf(xo)));
        int li = l2p[p * LSEQ + t];
        delay += occ / cap[li];
    }
    if (lane == 0) out[p] = delay;
}

// ============================================================
// Launch
// ============================================================
extern "C" void kernel_launch(void* const* d_in, const int* in_sizes, int n_in,
                              void* d_out, int out_size)
{
    const float* ft    = (const float*)d_in[0];
    const float* fpk   = (const float*)d_in[1];
    const float* fps   = (const float*)d_in[2];
    const float* cap   = (const float*)d_in[3];
    const int*   l2p   = (const int*)d_in[4];
    const int*   p2l   = (const int*)d_in[5];
    const float* pe_w1 = (const float*)d_in[6],  *pe_b1 = (const float*)d_in[7];
    const float* pe_w2 = (const float*)d_in[8],  *pe_b2 = (const float*)d_in[9];
    const float* le_w1 = (const float*)d_in[10], *le_b1 = (const float*)d_in[11];
    const float* le_w2 = (const float*)d_in[12], *le_b2 = (const float*)d_in[13];
    const float* pg_wx = (const float*)d_in[14], *pg_wh = (const float*)d_in[15];
    const float* pg_bx = (const float*)d_in[16], *pg_bh = (const float*)d_in[17];
    const float* lg_wx = (const float*)d_in[18], *lg_wh = (const float*)d_in[19];
    const float* lg_bx = (const float*)d_in[20], *lg_bh = (const float*)d_in[21];
    const float* ro_w1 = (const float*)d_in[22], *ro_b1 = (const float*)d_in[23];
    const float* ro_w2 = (const float*)d_in[24], *ro_b2 = (const float*)d_in[25];
    const float* ro_w3 = (const float*)d_in[26], *ro_b3 = (const float*)d_in[27];

    cudaFuncSetAttribute(link_proj_kernel,       cudaFuncAttributeMaxDynamicSharedMemorySize, HALF_SMEM_BYTES);
    cudaFuncSetAttribute(path_update_mma_kernel, cudaFuncAttributeMaxDynamicSharedMemorySize, MMA_SMEM_BYTES);
    cudaFuncSetAttribute(link_gru_kernel,        cudaFuncAttributeMaxDynamicSharedMemorySize, GRU_SMEM_BYTES);

    path_embed_kernel<<<(NP + 7) / 8, 256>>>(ft, fpk, fps, pe_w1, pe_b1, pe_w2, pe_b2);
    link_embed_kernel<<<(NL + 7) / 8, 256>>>(ft, cap, p2l, le_w1, le_b1, le_w2, le_b2);
    prepack_wh_kernel<<<(4 * 24 * 32 + 255) / 256, 256>>>(pg_wh);

    for (int it = 0; it < 8; it++) {
        link_proj_kernel<<<(NL + 39) / 40, 256, HALF_SMEM_BYTES>>>(pg_wx, pg_bx, pg_bh);
        path_update_mma_kernel<<<(NP + MCTA - 1) / MCTA, 128, MMA_SMEM_BYTES>>>(
            l2p, pg_bh, it == 0 ? 1 : 0);
        gather_sum_kernel<<<(NL + 3) / 4, 256>>>(p2l);
        link_gru_kernel<<<(NL + 39) / 40, 256, GRU_SMEM_BYTES>>>(
            lg_wx, lg_wh, lg_bx, lg_bh);
    }

    readout_kernel<<<(NP + 7) / 8, 256>>>(l2p, cap, ro_w1, ro_b1, ro_w2, ro_b2, ro_w3, ro_b3,
                                          (float*)d_out);
}

// round 12
// speedup vs baseline: 1.1663x; 1.0048x over previous
#include <cuda_runtime.h>
#include <math.h>
#include <stdint.h>

#define NP   50000
#define NL   10000
#define LSEQ 8
#define DEG  40
#define DD   64
#define FULL 0xffffffffu
#define MCTA 64           // paths per CTA in mma path kernel
#define ASTR 36           // u32 row stride of split-h arrays (bank-conflict-free)

// ---- persistent scratch (device globals: allocation-free) ----
__device__ float g_path_state[NP * DD];
__device__ float g_link_state[NL * DD];
__device__ float g_link_proj[NL * 192];              // x-proj with z/r biases folded in
__device__ float g_psseq[(size_t)NP * 8 * DD];       // slots = steps 1..8
__device__ uint4 g_Bpack[4 * 24 * 32];               // Wh split-bf16 fragment pack (48KB)

__device__ __forceinline__ float sigmoidf_(float x) { return 1.0f / (1.0f + expf(-x)); }

__device__ __forceinline__ float fast_ex2(float x) {
    float r; asm("ex2.approx.f32 %0, %1;" : "=f"(r) : "f"(x)); return r;
}
__device__ __forceinline__ float fast_rcp(float x) {
    float r; asm("rcp.approx.f32 %0, %1;" : "=f"(r) : "f"(x)); return r;
}
__device__ __forceinline__ float fsig(float x) {
    return fast_rcp(1.f + fast_ex2(-1.4426950408889634f * x));
}
__device__ __forceinline__ float ftanh(float x) {
    return 1.f - 2.f * fast_rcp(1.f + fast_ex2(2.8853900817779268f * x));
}
__device__ __forceinline__ float gru_one(float zp, float rp, float hp, float xh, float ho) {
    float z = fsig(zp), r = fsig(rp);
    float gg = ftanh(xh + r * hp);
    return z * ho + (1.f - z) * gg;
}

// pack lo->lower16, hi->upper16 bf16x2
__device__ __forceinline__ uint32_t pack_bf16x2(float lo, float hi) {
    uint32_t r; asm("cvt.rn.bf16x2.f32 %0, %1, %2;" : "=r"(r) : "f"(hi), "f"(lo)); return r;
}
__device__ __forceinline__ void split2(float a, float b, uint32_t& hi, uint32_t& lo) {
    hi = pack_bf16x2(a, b);
    float ra = a - __uint_as_float(hi << 16);
    float rb = b - __uint_as_float(hi & 0xffff0000u);
    lo = pack_bf16x2(ra, rb);
}

#define MMA_BF16(c, a0, a1, a2, a3, b0, b1)                                   \
    asm("mma.sync.aligned.m16n8k16.row.col.f32.bf16.bf16.f32 "                \
        "{%0,%1,%2,%3}, {%4,%5,%6,%7}, {%8,%9}, {%0,%1,%2,%3};"               \
        : "+f"((c)[0]), "+f"((c)[1]), "+f"((c)[2]), "+f"((c)[3])              \
        : "r"(a0), "r"(a1), "r"(a2), "r"(a3), "r"(b0), "r"(b1))

// ============================================================
// Path embedding: 3 -> 64 -> 64 MLP (relu), warp per path
// ============================================================
__global__ void path_embed_kernel(const float* __restrict__ ft, const float* __restrict__ fp,
                                  const float* __restrict__ fps,
                                  const float* __restrict__ w1, const float* __restrict__ b1,
                                  const float* __restrict__ w2, const float* __restrict__ b2)
{
    __shared__ float s_w2[DD * DD];
    __shared__ float s_w1[3 * DD];
    __shared__ float s_b1[DD];
    __shared__ float s_b2[DD];
    for (int i = threadIdx.x; i < DD * DD; i += blockDim.x) s_w2[i] = w2[i];
    for (int i = threadIdx.x; i < 3 * DD; i += blockDim.x) s_w1[i] = w1[i];
    for (int i = threadIdx.x; i < DD; i += blockDim.x) { s_b1[i] = b1[i]; s_b2[i] = b2[i]; }
    __syncthreads();

    int warp = threadIdx.x >> 5, lane = threadIdx.x & 31;
    int p = blockIdx.x * 8 + warp;
    if (p >= NP) return;
    int d0 = 2 * lane, d1 = d0 + 1;

    float in0 = ft[p] * 1e-4f;
    float in1 = fp[p] * 1e-3f;
    float in2 = fps[p] * 1e-3f;

    float ha = fmaxf(0.f, s_b1[d0] + in0 * s_w1[d0] + in1 * s_w1[DD + d0] + in2 * s_w1[2 * DD + d0]);
    float hb = fmaxf(0.f, s_b1[d1] + in0 * s_w1[d1] + in1 * s_w1[DD + d1] + in2 * s_w1[2 * DD + d1]);

    float oa = s_b2[d0], ob = s_b2[d1];
    #pragma unroll 8
    for (int kk = 0; kk < 32; kk++) {
        float ka = __shfl_sync(FULL, ha, kk);
        float kb = __shfl_sync(FULL, hb, kk);
        float2 wA = *(const float2*)&s_w2[(2 * kk) * DD + d0];
        float2 wB = *(const float2*)&s_w2[(2 * kk + 1) * DD + d0];
        oa += ka * wA.x + kb * wB.x;
        ob += ka * wA.y + kb * wB.y;
    }
    g_path_state[p * DD + d0] = fmaxf(0.f, oa);
    g_path_state[p * DD + d1] = fmaxf(0.f, ob);
}

// ============================================================
// Link embedding
// ============================================================
__global__ void link_embed_kernel(const float* __restrict__ ftraf, const float* __restrict__ cap,
                                  const int* __restrict__ p2l,
                                  const float* __restrict__ w1, const float* __restrict__ b1,
                                  const float* __restrict__ w2, const float* __restrict__ b2)
{
    __shared__ float s_w2[DD * DD];
    __shared__ float s_w1[2 * DD];
    __shared__ float s_b1[DD];
    __shared__ float s_b2[DD];
    for (int i = threadIdx.x; i < DD * DD; i += blockDim.x) s_w2[i] = w2[i];
    for (int i = threadIdx.x; i < 2 * DD; i += blockDim.x) s_w1[i] = w1[i];
    for (int i = threadIdx.x; i < DD; i += blockDim.x) { s_b1[i] = b1[i]; s_b2[i] = b2[i]; }
    __syncthreads();

    int warp = threadIdx.x >> 5, lane = threadIdx.x & 31;
    int l = blockIdx.x * 8 + warp;
    if (l >= NL) return;
    int d0 = 2 * lane, d1 = d0 + 1;

    float s = ftraf[p2l[(l * DEG + lane) * 2]];
    if (lane < DEG - 32) s += ftraf[p2l[(l * DEG + 32 + lane) * 2]];
    #pragma unroll
    for (int off = 16; off; off >>= 1) s += __shfl_xor_sync(FULL, s, off);

    float c = cap[l];
    float in0 = c * 1e-5f;
    float in1 = s / (c * 1e9f);

    float ha = fmaxf(0.f, s_b1[d0] + in0 * s_w1[d0] + in1 * s_w1[DD + d0]);
    float hb = fmaxf(0.f, s_b1[d1] + in0 * s_w1[d1] + in1 * s_w1[DD + d1]);

    float oa = s_b2[d0], ob = s_b2[d1];
    #pragma unroll 8
    for (int kk = 0; kk < 32; kk++) {
        float ka = __shfl_sync(FULL, ha, kk);
        float kb = __shfl_sync(FULL, hb, kk);
        float2 wA = *(const float2*)&s_w2[(2 * kk) * DD + d0];
        float2 wB = *(const float2*)&s_w2[(2 * kk + 1) * DD + d0];
        oa += ka * wA.x + kb * wB.x;
        ob += ka * wA.y + kb * wB.y;
    }
    g_link_state[l * DD + d0] = fmaxf(0.f, oa);
    g_link_state[l * DD + d1] = fmaxf(0.f, ob);
}

// ============================================================
// Prepack pg_wh into split-bf16 m16n8k16 B-fragment order.
// ============================================================
__global__ void prepack_wh_kernel(const float* __restrict__ wh)
{
    int i = blockIdx.x * 256 + threadIdx.x;
    if (i >= 4 * 24 * 32) return;
    int lane = i & 31;
    int nt = (i >> 5) % 24;
    int kt = i / (32 * 24);
    int q = lane & 3, g = lane >> 2;
    int n = nt * 8 + g;
    int k0 = kt * 16 + 2 * q;

    float2 f0 = make_float2(wh[k0 * 192 + n],       wh[(k0 + 1) * 192 + n]);
    float2 f1 = make_float2(wh[(k0 + 8) * 192 + n], wh[(k0 + 9) * 192 + n]);
    uint32_t b0h, b0l, b1h, b1l;
    split2(f0.x, f0.y, b0h, b0l);
    split2(f1.x, f1.y, b1h, b1l);
    g_Bpack[i] = make_uint4(b0h, b1h, b0l, b1l);
}

// ============================================================
// link_proj = link_state @ pg_wx + pg_bx (+ pg_bh folded for z/r)
// warp = 5 links -> 250 CTAs (single wave at 2 CTAs/SM)
// ============================================================
#define HALF_SMEM_BYTES ((DD * 192 + 192) * 4)

__global__ void __launch_bounds__(256, 2)
link_proj_kernel(const float* __restrict__ wx_g, const float* __restrict__ bx_g,
                 const float* __restrict__ bh_g)
{
    extern __shared__ float sm[];
    float* s_wx = sm;
    float* s_bx = sm + DD * 192;
    for (int i = threadIdx.x; i < DD * 192; i += 256) s_wx[i] = wx_g[i];
    if (threadIdx.x < 192)
        s_bx[threadIdx.x] = bx_g[threadIdx.x] +
                            (threadIdx.x < 128 ? bh_g[threadIdx.x] : 0.f);
    __syncthreads();

    int warp = threadIdx.x >> 5, lane = threadIdx.x & 31;
    int d0 = 2 * lane;
    int l0 = blockIdx.x * 40 + warp * 5;

    float h0[5], h1[5];
    #pragma unroll
    for (int b = 0; b < 5; b++) {
        int l = l0 + b;
        h0[b] = h1[b] = 0.f;
        if (l < NL) {
            float2 h = *(const float2*)&g_link_state[l * DD + d0];
            h0[b] = h.x; h1[b] = h.y;
        }
    }

    float pz0[5], pz1[5], pr0[5], pr1[5], ph0[5], ph1[5];
    #pragma unroll
    for (int b = 0; b < 5; b++) {
        pz0[b] = s_bx[d0];        pz1[b] = s_bx[d0 + 1];
        pr0[b] = s_bx[64 + d0];   pr1[b] = s_bx[64 + d0 + 1];
        ph0[b] = s_bx[128 + d0];  ph1[b] = s_bx[128 + d0 + 1];
    }
    #pragma unroll 4
    for (int kk = 0; kk < 32; kk++) {
        const float* wa = s_wx + (2 * kk) * 192;
        float2 za = *(const float2*)(wa + d0);
        float2 ra = *(const float2*)(wa + 64 + d0);
        float2 ha = *(const float2*)(wa + 128 + d0);
        float2 zb = *(const float2*)(wa + 192 + d0);
        float2 rb = *(const float2*)(wa + 192 + 64 + d0);
        float2 hb = *(const float2*)(wa + 192 + 128 + d0);
        #pragma unroll
        for (int b = 0; b < 5; b++) {
            float ka = __shfl_sync(FULL, h0[b], kk);
            float kb = __shfl_sync(FULL, h1[b], kk);
            pz0[b] += ka * za.x + kb * zb.x;  pz1[b] += ka * za.y + kb * zb.y;
            pr0[b] += ka * ra.x + kb * rb.x;  pr1[b] += ka * ra.y + kb * rb.y;
            ph0[b] += ka * ha.x + kb * hb.x;  ph1[b] += ka * ha.y + kb * hb.y;
        }
    }
    #pragma unroll
    for (int b = 0; b < 5; b++) {
        int l = l0 + b;
        if (l < NL) {
            *(float2*)&g_link_proj[l * 192 + d0]       = make_float2(pz0[b], pz1[b]);
            *(float2*)&g_link_proj[l * 192 + 64 + d0]  = make_float2(pr0[b], pr1[b]);
            *(float2*)&g_link_proj[l * 192 + 128 + d0] = make_float2(ph0[b], ph1[b]);
        }
    }
}

// ============================================================
// Path GRU via split-bf16 m16n8k16 mma. CTA = 64 paths, 4 warps,
// 3 CTAs/SM. N in two 32-col halves per step (C = [12][4]).
// z/r gate tiles use 2-term split (drop Alo*Bhi; sigmoid-attenuated),
// hh tiles keep exact 3-term split.
// ============================================================
#define PSM_A_HI  49152
#define PSM_A_LO  (PSM_A_HI + MCTA * ASTR * 4)
#define PSM_BHH   (PSM_A_LO + MCTA * ASTR * 4)
#define MMA_SMEM_BYTES (PSM_BHH + 64 * 4)

__global__ void __launch_bounds__(128, 3)
path_update_mma_kernel(const int* __restrict__ l2p, const float* __restrict__ bh_g, int first)
{
    extern __shared__ unsigned char smraw[];
    uint4*    s_B   = (uint4*)smraw;                      // 3072 uint4 = 48 KB
    uint32_t* s_Ahi = (uint32_t*)(smraw + PSM_A_HI);      // 64 x ASTR
    uint32_t* s_Alo = (uint32_t*)(smraw + PSM_A_LO);
    float*    s_bhh = (float*)(smraw + PSM_BHH);          // 64

    int tid = threadIdx.x;
    #pragma unroll
    for (int i = 0; i < 24; i++) s_B[tid + i * 128] = g_Bpack[tid + i * 128];
    if (tid < 64) s_bhh[tid] = bh_g[128 + tid];

    // prologue: load h rows (fp32), split to bf16x2 hi/lo arrays.
    int pbase = blockIdx.x * MCTA;
    {
        int r = tid >> 1, hf = tid & 1;        // 64 rows x 2 halves
        int p = pbase + r;
        int pc = p < NP ? p : NP - 1;
        const float* hsrc = (first ? &g_path_state[(size_t)pc * 64]
                                   : &g_psseq[((size_t)pc * 8 + 7) * 64]) + hf * 32;
        uint32_t* ah = &s_Ahi[r * ASTR + hf * 16];
        uint32_t* al = &s_Alo[r * ASTR + hf * 16];
        #pragma unroll
        for (int j = 0; j < 8; j++) {
            float4 v = *(const float4*)&hsrc[4 * j];
            uint32_t h0, l0, h1, l1;
            split2(v.x, v.y, h0, l0);
            split2(v.z, v.w, h1, l1);
            ah[2 * j] = h0; ah[2 * j + 1] = h1;
            al[2 * j] = l0; al[2 * j + 1] = l1;
        }
    }
    __syncthreads();

    int lane = tid & 31, warp = tid >> 5;
    int q = lane & 3, g = lane >> 2;
    int r0 = warp * 16 + g;                 // local rows r0, r0+8 (warp 0..3 covers 64)
    int p0 = pbase + r0, p1 = p0 + 8;
    int p0c = (p0 < NP) ? p0 : 0;
    int p1c = (p1 < NP) ? p1 : 0;

    uint32_t* A0hi = &s_Ahi[r0 * ASTR];
    uint32_t* A1hi = &s_Ahi[(r0 + 8) * ASTR];
    uint32_t* A0lo = &s_Alo[r0 * ASTR];
    uint32_t* A1lo = &s_Alo[(r0 + 8) * ASTR];

    for (int t = 0; t < LSEQ; t++) {
        int li0 = l2p[p0c * LSEQ + t];
        int li1 = l2p[p1c * LSEQ + t];
        const float* pr0 = &g_link_proj[li0 * 192];
        const float* pr1 = &g_link_proj[li1 * 192];

        uint32_t st_h[8], st_l[8];   // half-0 new-h stash (committed after half-1)

        #pragma unroll
        for (int hf2 = 0; hf2 < 2; hf2++) {
            float C[12][4];

            // C init: z tiles (c 0..3), r tiles (c 4..7) <- gathered
            // x-projection (biases pre-folded); hh tiles (c 8..11) <- 0.
            #pragma unroll
            for (int c = 0; c < 4; c++) {
                int col = (4 * hf2 + c) * 8 + 2 * q;
                float2 x0 = *(const float2*)&pr0[col];
                float2 x1 = *(const float2*)&pr1[col];
                C[c][0] = x0.x; C[c][1] = x0.y; C[c][2] = x1.x; C[c][3] = x1.y;
            }
            #pragma unroll
            for (int c = 0; c < 4; c++) {
                int col = (8 + 4 * hf2 + c) * 8 + 2 * q;
                float2 x0 = *(const float2*)&pr0[col];
                float2 x1 = *(const float2*)&pr1[col];
                C[4 + c][0] = x0.x; C[4 + c][1] = x0.y; C[4 + c][2] = x1.x; C[4 + c][3] = x1.y;
            }
            #pragma unroll
            for (int c = 8; c < 12; c++) {
                C[c][0] = 0.f; C[c][1] = 0.f; C[c][2] = 0.f; C[c][3] = 0.f;
            }

            // h @ Wh via split-bf16 (old h — untouched until both halves done)
            #pragma unroll
            for (int kt = 0; kt < 4; kt++) {
                int kp = kt * 8 + q;
                uint32_t a0h = A0hi[kp],     a1h = A1hi[kp];
                uint32_t a2h = A0hi[kp + 4], a3h = A1hi[kp + 4];
                uint32_t a0l = A0lo[kp],     a1l = A1lo[kp];
                uint32_t a2l = A0lo[kp + 4], a3l = A1lo[kp + 4];
                const uint4* Bk = s_B + kt * 24 * 32 + lane;
                #pragma unroll
                for (int c = 0; c < 12; c++) {
                    int gnt = (c < 4) ? (4 * hf2 + c)
                            : (c < 8) ? (8 + 4 * hf2 + c - 4)
                                      : (16 + 4 * hf2 + c - 8);
                    uint4 B = Bk[gnt * 32];
                    MMA_BF16(C[c], a0h, a1h, a2h, a3h, B.x, B.y);
                    MMA_BF16(C[c], a0h, a1h, a2h, a3h, B.z, B.w);
                    if (c >= 8)   // exact 3-term only for candidate (tanh) tiles
                        MMA_BF16(C[c], a0l, a1l, a2l, a3l, B.x, B.y);
                }
            }

            // half-epilogue: 4 column groups of 8 within this 32-col half
            #pragma unroll
            for (int j = 0; j < 4; j++) {
                int col = 32 * hf2 + 8 * j + 2 * q;    // global col 0..63
                int kp  = 16 * hf2 + 4 * j + q;        // h pair index
                float2 xh0 = *(const float2*)&pr0[128 + col];
                float2 xh1 = *(const float2*)&pr1[128 + col];
                float2 bhh = *(const float2*)&s_bhh[col];
                uint32_t ohi0 = A0hi[kp], ohi1 = A1hi[kp];
                uint32_t olo0 = A0lo[kp], olo1 = A1lo[kp];
                float ho00 = __uint_as_float(ohi0 << 16)         + __uint_as_float(olo0 << 16);
                float ho01 = __uint_as_float(ohi0 & 0xffff0000u) + __uint_as_float(olo0 & 0xffff0000u);
                float ho10 = __uint_as_float(ohi1 << 16)         + __uint_as_float(olo1 << 16);
                float ho11 = __uint_as_float(ohi1 & 0xffff0000u) + __uint_as_float(olo1 & 0xffff0000u);

                float n00 = gru_one(C[j][0], C[4 + j][0], C[8 + j][0] + bhh.x, xh0.x, ho00);
                float n01 = gru_one(C[j][1], C[4 + j][1], C[8 + j][1] + bhh.y, xh0.y, ho01);
                float n10 = gru_one(C[j][2], C[4 + j][2], C[8 + j][2] + bhh.x, xh1.x, ho10);
                float n11 = gru_one(C[j][3], C[4 + j][3], C[8 + j][3] + bhh.y, xh1.y, ho11);

                if (p0 < NP) *(float2*)&g_psseq[((size_t)p0 * 8 + t) * 64 + col] = make_float2(n00, n01);
                if (p1 < NP) *(float2*)&g_psseq[((size_t)p1 * 8 + t) * 64 + col] = make_float2(n10, n11);

                uint32_t nh0, nl0, nh1, nl1;
                split2(n00, n01, nh0, nl0);
                split2(n10, n11, nh1, nl1);
                if (hf2 == 0) {
                    st_h[2 * j] = nh0; st_h[2 * j + 1] = nh1;
                    st_l[2 * j] = nl0; st_l[2 * j + 1] = nl1;
                } else {
                    A0hi[kp] = nh0; A1hi[kp] = nh1;
                    A0lo[kp] = nl0; A1lo[kp] = nl1;
                }
            }
        }

        // commit half-0's new h (its MMA consumers are done)
        #pragma unroll
        for (int j = 0; j < 4; j++) {
            int kp = 4 * j + q;
            A0hi[kp] = st_h[2 * j]; A1hi[kp] = st_h[2 * j + 1];
            A0lo[kp] = st_l[2 * j]; A1lo[kp] = st_l[2 * j + 1];
        }
        __syncwarp();   // warp-private rows: order smem h writes before next step's reads
    }
}

// ============================================================
// Fused gather + link GRU: warp = 5 links, 40 links/CTA, 250 CTAs.
// Gathers DEG psseq rows per link directly into x, then one GRU step.
// Removes the path_sum global roundtrip and one launch per iteration.
// ============================================================
#define GG_IDX_OFF (2 * DD * 192 + 2 * 192)                  // float offset of idx area
#define GG_SMEM_BYTES ((2 * DD * 192 + 2 * 192) * 4 + 40 * DEG * 8)

__global__ void __launch_bounds__(256, 2)
link_gather_gru_kernel(const int* __restrict__ p2l,
                       const float* __restrict__ wx_g, const float* __restrict__ wh_g,
                       const float* __restrict__ bx_g, const float* __restrict__ bh_g)
{
    extern __shared__ float sm[];
    float* s_wx = sm;
    float* s_wh = sm + DD * 192;
    float* s_bx = s_wh + DD * 192;
    float* s_bh = s_bx + 192;
    int2*  s_idx = (int2*)(sm + GG_IDX_OFF);                 // 40 links x DEG
    for (int i = threadIdx.x; i < DD * 192; i += 256) { s_wx[i] = wx_g[i]; s_wh[i] = wh_g[i]; }
    if (threadIdx.x < 192) { s_bx[threadIdx.x] = bx_g[threadIdx.x]; s_bh[threadIdx.x] = bh_g[threadIdx.x]; }

    int lbase = blockIdx.x * 40;
    for (int i = threadIdx.x; i < 40 * DEG; i += 256) {
        int ll = lbase + i / DEG;
        if (ll < NL) s_idx[i] = ((const int2*)p2l)[ll * DEG + (i % DEG)];
    }
    __syncthreads();

    int warp = threadIdx.x >> 5, lane = threadIdx.x & 31;
    int d0 = 2 * lane;
    int l0 = lbase + warp * 5;

    float h0[5], h1[5], x0[5], x1[5];
    #pragma unroll
    for (int b = 0; b < 5; b++) {
        int l = l0 + b;
        h0[b] = h1[b] = x0[b] = x1[b] = 0.f;
        if (l < NL) {
            float2 h = *(const float2*)&g_link_state[l * DD + d0];
            h0[b] = h.x; h1[b] = h.y;
            const int2* idx = &s_idx[(warp * 5 + b) * DEG];
            float sx = 0.f, sy = 0.f;
            #pragma unroll 8
            for (int e = 0; e < DEG; e++) {
                int2 pe = idx[e];
                float2 v = *(const float2*)&g_psseq[((size_t)pe.x * 8 + (pe.y - 1)) * DD + d0];
                sx += v.x; sy += v.y;
            }
            x0[b] = sx; x1[b] = sy;
        }
    }

    float bz0 = s_bx[d0] + s_bh[d0],               bz1 = s_bx[d0 + 1] + s_bh[d0 + 1];
    float br0 = s_bx[64 + d0] + s_bh[64 + d0],     br1 = s_bx[64 + d0 + 1] + s_bh[64 + d0 + 1];
    float bxh0 = s_bx[128 + d0],  bxh1 = s_bx[128 + d0 + 1];
    float bhh0 = s_bh[128 + d0],  bhh1 = s_bh[128 + d0 + 1];

    float az0[5], az1[5], ar0[5], ar1[5], ax0[5], ax1[5], ah0[5], ah1[5];
    #pragma unroll
    for (int b = 0; b < 5; b++) {
        az0[b] = bz0;  az1[b] = bz1;  ar0[b] = br0;  ar1[b] = br1;
        ax0[b] = bxh0; ax1[b] = bxh1; ah0[b] = bhh0; ah1[b] = bhh1;
    }
    #pragma unroll 2
    for (int kk = 0; kk < 32; kk++) {
        const float* wxa = s_wx + (2 * kk) * 192;
        const float* wha = s_wh + (2 * kk) * 192;
        float2 xza = *(const float2*)(wxa + d0);
        float2 xra = *(const float2*)(wxa + 64 + d0);
        float2 xha = *(const float2*)(wxa + 128 + d0);
        float2 xzb = *(const float2*)(wxa + 192 + d0);
        float2 xrb = *(const float2*)(wxa + 192 + 64 + d0);
        float2 xhb = *(const float2*)(wxa + 192 + 128 + d0);
        float2 hza = *(const float2*)(wha + d0);
        float2 hra = *(const float2*)(wha + 64 + d0);
        float2 hha = *(const float2*)(wha + 128 + d0);
        float2 hzb = *(const float2*)(wha + 192 + d0);
        float2 hrb = *(const float2*)(wha + 192 + 64 + d0);
        float2 hhb = *(const float2*)(wha + 192 + 128 + d0);
        #pragma unroll
        for (int b = 0; b < 5; b++) {
            float xka = __shfl_sync(FULL, x0[b], kk);
            float xkb = __shfl_sync(FULL, x1[b], kk);
            float hka = __shfl_sync(FULL, h0[b], kk);
            float hkb = __shfl_sync(FULL, h1[b], kk);
            az0[b] += xka * xza.x + xkb * xzb.x + hka * hza.x + hkb * hzb.x;
            az1[b] += xka * xza.y + xkb * xzb.y + hka * hza.y + hkb * hzb.y;
            ar0[b] += xka * xra.x + xkb * xrb.x + hka * hra.x + hkb * hrb.x;
            ar1[b] += xka * xra.y + xkb * xrb.y + hka * hra.y + hkb * hrb.y;
            ax0[b] += xka * xha.x + xkb * xhb.x;
            ax1[b] += xka * xha.y + xkb * xhb.y;
            ah0[b] += hka * hha.x + hkb * hhb.x;
            ah1[b] += hka * hha.y + hkb * hhb.y;
        }
    }
    #pragma unroll
    for (int b = 0; b < 5; b++) {
        int l = l0 + b;
        if (l < NL) {
            float z0 = sigmoidf_(az0[b]), z1 = sigmoidf_(az1[b]);
            float r0 = sigmoidf_(ar0[b]), r1 = sigmoidf_(ar1[b]);
            float g0 = tanhf(ax0[b] + r0 * ah0[b]);
            float g1 = tanhf(ax1[b] + r1 * ah1[b]);
            float n0 = z0 * h0[b] + (1.f - z0) * g0;
            float n1 = z1 * h1[b] + (1.f - z1) * g1;
            *(float2*)&g_link_state[l * DD + d0] = make_float2(n0, n1);
        }
    }
}

// ============================================================
// Readout
// ============================================================
__global__ void readout_kernel(const int* __restrict__ l2p, const float* __restrict__ cap,
                               const float* __restrict__ w1, const float* __restrict__ b1,
                               const float* __restrict__ w2, const float* __restrict__ b2,
                               const float* __restrict__ w3, const float* __restrict__ b3,
                               float* __restrict__ out)
{
    __shared__ float s_w1[DD * 32];
    __shared__ float s_w2[32 * 16];
    __shared__ float s_w3[16];
    __shared__ float s_b1[32];
    __shared__ float s_b2[16];
    __shared__ float s_b3;
    for (int i = threadIdx.x; i < DD * 32; i += blockDim.x) s_w1[i] = w1[i];
    for (int i = threadIdx.x; i < 32 * 16; i += blockDim.x) s_w2[i] = w2[i];
    if (threadIdx.x < 16) { s_w3[threadIdx.x] = w3[threadIdx.x]; s_b2[threadIdx.x] = b2[threadIdx.x]; }
    if (threadIdx.x < 32) s_b1[threadIdx.x] = b1[threadIdx.x];
    if (threadIdx.x == 0) s_b3 = b3[0];
    __syncthreads();

    int warp = threadIdx.x >> 5, lane = threadIdx.x & 31;
    int p = blockIdx.x * 8 + warp;
    if (p >= NP) return;
    int d0 = 2 * lane;

    float delay = 0.f;
    for (int t = 0; t < LSEQ; t++) {
        float2 in = *(const float2*)&g_psseq[((size_t)p * 8 + t) * DD + d0];
        float a = s_b1[lane];
        #pragma unroll 8
        for (int kk = 0; kk < 32; kk++) {
            float ka = __shfl_sync(FULL, in.x, kk);
            float kb = __shfl_sync(FULL, in.y, kk);
            a += ka * s_w1[(2 * kk) * 32 + lane] + kb * s_w1[(2 * kk + 1) * 32 + lane];
        }
        a = fmaxf(a, 0.f);
        float c = s_b2[lane & 15];
        #pragma unroll 8
        for (int k = 0; k < 32; k++) {
            float hk = __shfl_sync(FULL, a, k);
            c += hk * s_w2[k * 16 + (lane & 15)];
        }
        c = fmaxf(c, 0.f);
        float term = (lane < 16) ? c * s_w3[lane] : 0.f;
        #pragma unroll
        for (int off = 16; off; off >>= 1) term += __shfl_xor_sync(FULL, term, off);
        float xo = term + s_b3;
        float occ = fmaxf(xo, 0.f) + log1pf(expf(-fabsf(xo)));
        int li = l2p[p * LSEQ + t];
        delay += occ / cap[li];
    }
    if (lane == 0) out[p] = delay;
}

// ============================================================
// Launch
// ============================================================
extern "C" void kernel_launch(void* const* d_in, const int* in_sizes, int n_in,
                              void* d_out, int out_size)
{
    const float* ft    = (const float*)d_in[0];
    const float* fpk   = (const float*)d_in[1];
    const float* fps   = (const float*)d_in[2];
    const float* cap   = (const float*)d_in[3];
    const int*   l2p   = (const int*)d_in[4];
    const int*   p2l   = (const int*)d_in[5];
    const float* pe_w1 = (const float*)d_in[6],  *pe_b1 = (const float*)d_in[7];
    const float* pe_w2 = (const float*)d_in[8],  *pe_b2 = (const float*)d_in[9];
    const float* le_w1 = (const float*)d_in[10], *le_b1 = (const float*)d_in[11];
    const float* le_w2 = (const float*)d_in[12], *le_b2 = (const float*)d_in[13];
    const float* pg_wx = (const float*)d_in[14], *pg_wh = (const float*)d_in[15];
    const float* pg_bx = (const float*)d_in[16], *pg_bh = (const float*)d_in[17];
    const float* lg_wx = (const float*)d_in[18], *lg_wh = (const float*)d_in[19];
    const float* lg_bx = (const float*)d_in[20], *lg_bh = (const float*)d_in[21];
    const float* ro_w1 = (const float*)d_in[22], *ro_b1 = (const float*)d_in[23];
    const float* ro_w2 = (const float*)d_in[24], *ro_b2 = (const float*)d_in[25];
    const float* ro_w3 = (const float*)d_in[26], *ro_b3 = (const float*)d_in[27];

    cudaFuncSetAttribute(link_proj_kernel,       cudaFuncAttributeMaxDynamicSharedMemorySize, HALF_SMEM_BYTES);
    cudaFuncSetAttribute(path_update_mma_kernel, cudaFuncAttributeMaxDynamicSharedMemorySize, MMA_SMEM_BYTES);
    cudaFuncSetAttribute(link_gather_gru_kernel, cudaFuncAttributeMaxDynamicSharedMemorySize, GG_SMEM_BYTES);

    path_embed_kernel<<<(NP + 7) / 8, 256>>>(ft, fpk, fps, pe_w1, pe_b1, pe_w2, pe_b2);
    link_embed_kernel<<<(NL + 7) / 8, 256>>>(ft, cap, p2l, le_w1, le_b1, le_w2, le_b2);
    prepack_wh_kernel<<<(4 * 24 * 32 + 255) / 256, 256>>>(pg_wh);

    for (int it = 0; it < 8; it++) {
        link_proj_kernel<<<(NL + 39) / 40, 256, HALF_SMEM_BYTES>>>(pg_wx, pg_bx, pg_bh);
        path_update_mma_kernel<<<(NP + MCTA - 1) / MCTA, 128, MMA_SMEM_BYTES>>>(
            l2p, pg_bh, it == 0 ? 1 : 0);
        link_gather_gru_kernel<<<(NL + 39) / 40, 256, GG_SMEM_BYTES>>>(
            p2l, lg_wx, lg_wh, lg_bx, lg_bh);
    }

    readout_kernel<<<(NP + 7) / 8, 256>>>(l2p, cap, ro_w1, ro_b1, ro_w2, ro_b2, ro_w3, ro_b3,
                                          (float*)d_out);
}